// round 1
// baseline (speedup 1.0000x reference)
#include <cuda_runtime.h>
#include <math.h>

#define BATCH 8
#define NCIN 8
#define HID 64
#define LNK 9
#define HH 120
#define WW 120
#define HW (HH*WW)      // 14400
#define C3 (3*HID)      // 192

// -------- scratch (device globals; no allocation in kernel_launch) --------
__device__ float  g_f[BATCH*32*HW];          // 14.7 MB  relu(i2f+h2f)
__device__ float  g_flows[BATCH*2*LNK*HW];   //  8.3 MB
__device__ float  g_i2h[(size_t)BATCH*C3*HW];// 88.5 MB
__device__ float4 g_hT4[(size_t)BATCH*HW*16];// 29.5 MB  h_prev transposed to [b][p][c]

// ---------------- transpose h_prev NCHW -> NHWC (float4-friendly) ----------
__global__ void k_transpose(const float* __restrict__ hp)
{
    __shared__ float t[32][33];
    int b  = blockIdx.z;
    int c0 = blockIdx.y * 32;
    int p0 = blockIdx.x * 32;
    int tx = threadIdx.x, ty = threadIdx.y;   // (32,8)
    float* hT = (float*)g_hT4;
#pragma unroll
    for (int k = 0; k < 4; k++) {
        int c = c0 + ty + k*8;
        t[ty + k*8][tx] = hp[((size_t)b*HID + c)*HW + p0 + tx];
    }
    __syncthreads();
#pragma unroll
    for (int k = 0; k < 4; k++) {
        int p = p0 + ty + k*8;
        hT[((size_t)b*HW + p)*HID + c0 + tx] = t[tx][ty + k*8];
    }
}

// ---------------- f = relu(conv5x5(x;i2f) + conv5x5(h_prev;h2f)) -----------
__global__ __launch_bounds__(480) void k_f(
    const float* __restrict__ x, const float* __restrict__ hp,
    const float* __restrict__ i2f_w, const float* __restrict__ i2f_b,
    const float* __restrict__ h2f_w, const float* __restrict__ h2f_b)
{
    __shared__ float sp[8*124];
    __shared__ float ws[32*25];
    int b   = blockIdx.y;
    int ty0 = blockIdx.x * 4;
    int tid = threadIdx.x;
    int py = tid / 120, px = tid % 120;
    int y = ty0 + py;

    float acc[32];
#pragma unroll
    for (int i = 0; i < 32; i++) acc[i] = 0.f;

    for (int vic = 0; vic < 72; vic++) {
        __syncthreads();
        const float* src = (vic < 8) ? (x  + ((size_t)b*NCIN + vic)*HW)
                                     : (hp + ((size_t)b*HID + (vic-8))*HW);
        for (int idx = tid; idx < 8*124; idx += 480) {
            int r = idx / 124, col = idx % 124;
            int gy = ty0 - 2 + r, gx = col - 2;
            float v = 0.f;
            if (gy >= 0 && gy < HH && gx >= 0 && gx < WW) v = src[gy*WW + gx];
            sp[idx] = v;
        }
        const float* wsrc = (vic < 8) ? (i2f_w + vic*25) : (h2f_w + (vic-8)*25);
        int wstride = (vic < 8) ? (NCIN*25) : (HID*25);
        for (int idx = tid; idx < 800; idx += 480) {
            int oc = idx / 25, t = idx % 25;
            ws[idx] = wsrc[(size_t)oc*wstride + t];
        }
        __syncthreads();

        float pr[25];
#pragma unroll
        for (int dy = 0; dy < 5; dy++)
#pragma unroll
            for (int dx = 0; dx < 5; dx++)
                pr[dy*5+dx] = sp[(py+dy)*124 + px + dx];
#pragma unroll
        for (int oc = 0; oc < 32; oc++) {
#pragma unroll
            for (int t = 0; t < 25; t++)
                acc[oc] += ws[oc*25 + t] * pr[t];
        }
    }
#pragma unroll
    for (int oc = 0; oc < 32; oc++) {
        float v = acc[oc] + __ldg(&i2f_b[oc]) + __ldg(&h2f_b[oc]);
        g_f[((size_t)b*32 + oc)*HW + y*WW + px] = fmaxf(v, 0.f);
    }
}

// ---------------- flows = conv5x5(f; flows_w) -----------------------------
__global__ __launch_bounds__(480) void k_flows(
    const float* __restrict__ flows_w, const float* __restrict__ flows_b)
{
    __shared__ float sp[8*124];
    __shared__ float ws[18*25];
    int b   = blockIdx.y;
    int ty0 = blockIdx.x * 4;
    int tid = threadIdx.x;
    int py = tid / 120, px = tid % 120;
    int y = ty0 + py;

    float acc[18];
#pragma unroll
    for (int i = 0; i < 18; i++) acc[i] = 0.f;

    for (int ic = 0; ic < 32; ic++) {
        __syncthreads();
        const float* src = g_f + ((size_t)b*32 + ic)*HW;
        for (int idx = tid; idx < 8*124; idx += 480) {
            int r = idx / 124, col = idx % 124;
            int gy = ty0 - 2 + r, gx = col - 2;
            float v = 0.f;
            if (gy >= 0 && gy < HH && gx >= 0 && gx < WW) v = src[gy*WW + gx];
            sp[idx] = v;
        }
        for (int idx = tid; idx < 450; idx += 480)
            ws[idx] = flows_w[(size_t)(idx/25)*(32*25) + ic*25 + (idx%25)];
        __syncthreads();

        float pr[25];
#pragma unroll
        for (int dy = 0; dy < 5; dy++)
#pragma unroll
            for (int dx = 0; dx < 5; dx++)
                pr[dy*5+dx] = sp[(py+dy)*124 + px + dx];
#pragma unroll
        for (int oc = 0; oc < 18; oc++) {
#pragma unroll
            for (int t = 0; t < 25; t++)
                acc[oc] += ws[oc*25 + t] * pr[t];
        }
    }
#pragma unroll
    for (int oc = 0; oc < 18; oc++)
        g_flows[((size_t)b*(2*LNK) + oc)*HW + y*WW + px] = acc[oc] + __ldg(&flows_b[oc]);
}

// ---------------- i2h = conv3x3(x; i2h_w) ---------------------------------
__global__ __launch_bounds__(480) void k_i2h(
    const float* __restrict__ x,
    const float* __restrict__ i2h_w, const float* __restrict__ i2h_b)
{
    __shared__ float sp[8*6*124];   // 5952 floats
    __shared__ float ws[64*72];     // 4608 floats
    int b   = blockIdx.y;
    int ty0 = blockIdx.x * 4;
    int tid = threadIdx.x;
    int py = tid / 120, px = tid % 120;
    int y = ty0 + py;

    for (int idx = tid; idx < 8*744; idx += 480) {
        int ic = idx / 744;
        int rem = idx % 744;
        int r = rem / 124, col = rem % 124;
        int gy = ty0 - 1 + r, gx = col - 1;
        float v = 0.f;
        if (gy >= 0 && gy < HH && gx >= 0 && gx < WW)
            v = x[((size_t)b*NCIN + ic)*HW + gy*WW + gx];
        sp[idx] = v;
    }
    __syncthreads();

    float pr[72];
#pragma unroll
    for (int ic = 0; ic < 8; ic++)
#pragma unroll
        for (int dy = 0; dy < 3; dy++)
#pragma unroll
            for (int dx = 0; dx < 3; dx++)
                pr[ic*9 + dy*3 + dx] = sp[ic*744 + (py+dy)*124 + px + dx];

    for (int c0 = 0; c0 < C3; c0 += 64) {
        for (int idx = tid; idx < 64*72; idx += 480)
            ws[idx] = i2h_w[(size_t)c0*72 + idx];
        __syncthreads();
        for (int j = 0; j < 64; j++) {
            float a0 = 0.f, a1 = 0.f, a2 = 0.f, a3 = 0.f;
#pragma unroll
            for (int t = 0; t < 72; t += 4) {
                a0 += ws[j*72 + t    ] * pr[t    ];
                a1 += ws[j*72 + t + 1] * pr[t + 1];
                a2 += ws[j*72 + t + 2] * pr[t + 2];
                a3 += ws[j*72 + t + 3] * pr[t + 3];
            }
            g_i2h[((size_t)b*C3 + c0 + j)*HW + y*WW + px] =
                (a0 + a1) + (a2 + a3) + __ldg(&i2h_b[c0 + j]);
        }
        __syncthreads();
    }
}

// ---------------- fused warp(x9) + 1x1 conv + GRU gates -------------------
#define SW_STRIDE 193
#define SO_STRIDE 65
#define SMEM_MAIN_FLOATS (12480 + 4096 + 128)

__global__ __launch_bounds__(256) void k_main(
    const float* __restrict__ hp,
    const float* __restrict__ h2h_w, const float* __restrict__ h2h_b,
    float* __restrict__ out)
{
    extern __shared__ float sm[];
    float* swt = sm;                 // weights [c][o] stride 193 (12352 used); epilogue h2h [o][px] stride 65 (12480)
    float* wsh = sm + 12480;         // warped  [c][px]  64x64
    float* fsh = sm + 12480 + 4096;  // flow sx/sy per px (2x64)

    int b   = blockIdx.y;
    int p0  = blockIdx.x * 64;
    int tid = threadIdx.x;
    int og = tid >> 3, pg = tid & 7;
    int o0 = og * 6;

    float acc[6][8];
#pragma unroll
    for (int k = 0; k < 6; k++)
#pragma unroll
        for (int j = 0; j < 8; j++) acc[k][j] = 0.f;

    const float4* hT4 = g_hT4 + (size_t)b*HW*16;

    for (int l = 0; l < LNK; l++) {
        if (tid < 64) {
            fsh[tid]      = g_flows[((size_t)b*(2*LNK) + 2*l    )*HW + p0 + tid];
            fsh[64 + tid] = g_flows[((size_t)b*(2*LNK) + 2*l + 1)*HW + p0 + tid];
        }
#pragma unroll 4
        for (int idx = tid; idx < 12288; idx += 256) {
            int o = idx >> 6, c = idx & 63;
            swt[c*SW_STRIDE + o] = h2h_w[(size_t)o*576 + l*64 + c];
        }
        __syncthreads();

        // gather warped tile: 16 channel-quads x 64 px
#pragma unroll
        for (int it = 0; it < 4; it++) {
            int item = it*256 + tid;
            int px = item & 63, cg = item >> 6;
            int p = p0 + px;
            int yc = p / WW, xc = p - yc*WW;
            float sx = (float)xc + fsh[px];
            float sy = (float)yc + fsh[64 + px];
            float fx = floorf(sx), fy = floorf(sy);
            float wx1 = sx - fx, wy1 = sy - fy;
            float wx0 = 1.f - wx1, wy0 = 1.f - wy1;
            int ix0 = (int)fx, iy0 = (int)fy;
            bool vx0 = (ix0 >= 0) && (ix0 < WW);
            bool vx1 = (ix0 >= -1) && (ix0 < WW - 1);
            bool vy0 = (iy0 >= 0) && (iy0 < HH);
            bool vy1 = (iy0 >= -1) && (iy0 < HH - 1);
            float4 z = make_float4(0.f, 0.f, 0.f, 0.f);
            float4 v00 = z, v01 = z, v10 = z, v11 = z;
            if (vy0) {
                int rb = iy0 * WW;
                if (vx0) v00 = hT4[(size_t)(rb + ix0    )*16 + cg];
                if (vx1) v01 = hT4[(size_t)(rb + ix0 + 1)*16 + cg];
            }
            if (vy1) {
                int rb = (iy0 + 1) * WW;
                if (vx0) v10 = hT4[(size_t)(rb + ix0    )*16 + cg];
                if (vx1) v11 = hT4[(size_t)(rb + ix0 + 1)*16 + cg];
            }
            float w00 = wy0*wx0, w01 = wy0*wx1, w10 = wy1*wx0, w11 = wy1*wx1;
            int cb = cg * 4;
            wsh[(cb    )*64 + px] = w00*v00.x + w01*v01.x + w10*v10.x + w11*v11.x;
            wsh[(cb + 1)*64 + px] = w00*v00.y + w01*v01.y + w10*v10.y + w11*v11.y;
            wsh[(cb + 2)*64 + px] = w00*v00.z + w01*v01.z + w10*v10.z + w11*v11.z;
            wsh[(cb + 3)*64 + px] = w00*v00.w + w01*v01.w + w10*v10.w + w11*v11.w;
        }
        __syncthreads();

        // GEMM chunk: K=64 for this link
#pragma unroll 2
        for (int c = 0; c < 64; c++) {
            float4 va = *(const float4*)&wsh[c*64 + pg*8];
            float4 vb = *(const float4*)&wsh[c*64 + pg*8 + 4];
#pragma unroll
            for (int k = 0; k < 6; k++) {
                float w = swt[c*SW_STRIDE + o0 + k];
                acc[k][0] += w * va.x;  acc[k][1] += w * va.y;
                acc[k][2] += w * va.z;  acc[k][3] += w * va.w;
                acc[k][4] += w * vb.x;  acc[k][5] += w * vb.y;
                acc[k][6] += w * vb.z;  acc[k][7] += w * vb.w;
            }
        }
        __syncthreads();
    }

    // stash h2h result (+bias) to shared so gates can mix r/u/m channels
#pragma unroll
    for (int k = 0; k < 6; k++) {
        float bias = __ldg(&h2h_b[o0 + k]);
#pragma unroll
        for (int j = 0; j < 8; j++)
            swt[(o0 + k)*SO_STRIDE + pg*8 + j] = acc[k][j] + bias;
    }
    __syncthreads();

    const float* i2hb = g_i2h + (size_t)b*C3*HW;
#pragma unroll
    for (int k = 0; k < 16; k++) {
        int idx = k*256 + tid;          // 0..4095  (64 ch x 64 px)
        int c = idx >> 6, px = idx & 63;
        int p = p0 + px;
        float hr = swt[(c      )*SO_STRIDE + px];
        float hu = swt[(c +  64)*SO_STRIDE + px];
        float hm = swt[(c + 128)*SO_STRIDE + px];
        float ir = i2hb[(size_t)(c      )*HW + p];
        float iu = i2hb[(size_t)(c +  64)*HW + p];
        float im = i2hb[(size_t)(c + 128)*HW + p];
        float hpv = hp[((size_t)b*HID + c)*HW + p];
        float rg = 1.f / (1.f + expf(-(ir + hr)));
        float ug = 1.f / (1.f + expf(-(iu + hu)));
        float nm = tanhf(im + rg * hm);
        out[((size_t)b*HID + c)*HW + p] = ug * hpv + (1.f - ug) * nm;
    }
}

// ---------------- launch ---------------------------------------------------
extern "C" void kernel_launch(void* const* d_in, const int* in_sizes, int n_in,
                              void* d_out, int out_size)
{
    const float* x       = (const float*)d_in[0];
    const float* h_prev  = (const float*)d_in[1];
    const float* i2h_w   = (const float*)d_in[2];
    const float* i2h_b   = (const float*)d_in[3];
    const float* h2h_w   = (const float*)d_in[4];
    const float* h2h_b   = (const float*)d_in[5];
    const float* i2f_w   = (const float*)d_in[6];
    const float* i2f_b   = (const float*)d_in[7];
    const float* h2f_w   = (const float*)d_in[8];
    const float* h2f_b   = (const float*)d_in[9];
    const float* flows_w = (const float*)d_in[10];
    const float* flows_b = (const float*)d_in[11];
    float* out = (float*)d_out;

    cudaFuncSetAttribute(k_main, cudaFuncAttributeMaxDynamicSharedMemorySize,
                         SMEM_MAIN_FLOATS * (int)sizeof(float));

    dim3 gt(HW/32, HID/32, BATCH);
    k_transpose<<<gt, dim3(32, 8)>>>(h_prev);

    dim3 gc(HH/4, BATCH);
    k_f<<<gc, 480>>>(x, h_prev, i2f_w, i2f_b, h2f_w, h2f_b);
    k_i2h<<<gc, 480>>>(x, i2h_w, i2h_b);
    k_flows<<<gc, 480>>>(flows_w, flows_b);

    dim3 gm(HW/64, BATCH);
    k_main<<<gm, 256, SMEM_MAIN_FLOATS * (int)sizeof(float)>>>(h_prev, h2h_w, h2h_b, out);
}

// round 2
// speedup vs baseline: 1.2837x; 1.2837x over previous
#include <cuda_runtime.h>
#include <math.h>

#define BATCH 8
#define NCIN 8
#define HID 64
#define LNK 9
#define HH 120
#define WW 120
#define HW (HH*WW)      // 14400
#define C3 (3*HID)      // 192

// -------- scratch (device globals; no allocation in kernel_launch) --------
__device__ float  g_f[BATCH*32*HW];          // 14.7 MB  relu(i2f+h2f)
__device__ float  g_flows[BATCH*2*LNK*HW];   //  8.3 MB
__device__ float  g_i2h[(size_t)BATCH*C3*HW];// 88.5 MB
__device__ float4 g_hT4[(size_t)BATCH*HW*16];// 29.5 MB  h_prev transposed to [b][p][c]

// ---------------- transpose h_prev NCHW -> NHWC (float4-friendly) ----------
__global__ void k_transpose(const float* __restrict__ hp)
{
    __shared__ float t[32][33];
    int b  = blockIdx.z;
    int c0 = blockIdx.y * 32;
    int p0 = blockIdx.x * 32;
    int tx = threadIdx.x, ty = threadIdx.y;   // (32,8)
    float* hT = (float*)g_hT4;
#pragma unroll
    for (int k = 0; k < 4; k++) {
        int c = c0 + ty + k*8;
        t[ty + k*8][tx] = hp[((size_t)b*HID + c)*HW + p0 + tx];
    }
    __syncthreads();
#pragma unroll
    for (int k = 0; k < 4; k++) {
        int p = p0 + ty + k*8;
        hT[((size_t)b*HW + p)*HID + c0 + tx] = t[tx][ty + k*8];
    }
}

// ==========================================================================
// f = relu(conv5x5(x;i2f) + conv5x5(h_prev;h2f))
// tile: 4 rows x 60 cols. threads 240 = 60 px-threads (4 px each) x 4 oc-grps
// (8 oc each). 9 chunks of 8 input channels.
// ==========================================================================
__global__ __launch_bounds__(240, 2) void k_f(
    const float* __restrict__ x, const float* __restrict__ hp,
    const float* __restrict__ i2f_w, const float* __restrict__ i2f_b,
    const float* __restrict__ h2f_w, const float* __restrict__ h2f_b)
{
    __shared__ float sp[8][8*68];     // 8 ch, 8 rows, stride 68 (64 used)
    __shared__ float ws[8*25*32];     // [(ic*25+t)*32 + oc]

    int b   = blockIdx.z;
    int ty0 = blockIdx.y * 4;
    int c0  = blockIdx.x * 60;
    int tid = threadIdx.x;
    int ocg = tid / 60;               // 0..3
    int pt  = tid % 60;
    int r   = pt / 15;                // 0..3
    int cq  = (pt % 15) * 4;          // 0..56
    int o0  = ocg * 8;

    float acc[8][4];
#pragma unroll
    for (int k = 0; k < 8; k++)
#pragma unroll
        for (int j = 0; j < 4; j++) acc[k][j] = 0.f;

    for (int chunk = 0; chunk < 9; chunk++) {
        __syncthreads();
        const float* src = (chunk == 0) ? (x + (size_t)b*NCIN*HW)
                                        : (hp + ((size_t)b*HID + (chunk-1)*8)*HW);
        for (int idx = tid; idx < 8*512; idx += 240) {
            int ch = idx >> 9, rem = idx & 511;
            int row = rem >> 6, col = rem & 63;
            int gy = ty0 - 2 + row, gx = c0 - 2 + col;
            float v = 0.f;
            if (gy >= 0 && gy < HH && gx >= 0 && gx < WW)
                v = src[(size_t)ch*HW + gy*WW + gx];
            sp[ch][row*68 + col] = v;
        }
        for (int idx = tid; idx < 6400; idx += 240) {
            int oc = idx & 31, rest = idx >> 5;
            int ic = rest / 25, t = rest % 25;
            float v;
            if (chunk == 0) v = i2f_w[(size_t)oc*(NCIN*25) + ic*25 + t];
            else            v = h2f_w[(size_t)oc*(HID*25) + ((chunk-1)*8 + ic)*25 + t];
            ws[idx] = v;
        }
        __syncthreads();

#pragma unroll 2
        for (int ic = 0; ic < 8; ic++) {
            float pr[5][8];
#pragma unroll
            for (int dy = 0; dy < 5; dy++) {
                float4 a = *(const float4*)&sp[ic][(r+dy)*68 + cq];
                float4 bb = *(const float4*)&sp[ic][(r+dy)*68 + cq + 4];
                pr[dy][0]=a.x; pr[dy][1]=a.y; pr[dy][2]=a.z; pr[dy][3]=a.w;
                pr[dy][4]=bb.x; pr[dy][5]=bb.y; pr[dy][6]=bb.z; pr[dy][7]=bb.w;
            }
#pragma unroll
            for (int t = 0; t < 25; t++) {
                int dy = t / 5, dx = t % 5;
                const float* wb = &ws[(ic*25 + t)*32 + o0];
                float4 w0 = *(const float4*)wb;
                float4 w1 = *(const float4*)(wb + 4);
                float wv[8] = {w0.x,w0.y,w0.z,w0.w,w1.x,w1.y,w1.z,w1.w};
#pragma unroll
                for (int k = 0; k < 8; k++)
#pragma unroll
                    for (int j = 0; j < 4; j++)
                        acc[k][j] += wv[k] * pr[dy][dx + j];
            }
        }
    }

#pragma unroll
    for (int k = 0; k < 8; k++) {
        float bias = __ldg(&i2f_b[o0+k]) + __ldg(&h2f_b[o0+k]);
        float4 o;
        o.x = fmaxf(acc[k][0] + bias, 0.f);
        o.y = fmaxf(acc[k][1] + bias, 0.f);
        o.z = fmaxf(acc[k][2] + bias, 0.f);
        o.w = fmaxf(acc[k][3] + bias, 0.f);
        *(float4*)&g_f[((size_t)b*32 + o0 + k)*HW + (ty0+r)*WW + c0 + cq] = o;
    }
}

// ==========================================================================
// flows = conv5x5(f; flows_w): 32 ch -> 18.
// tile 4 rows x 120 cols. threads 240 = 120 px-threads (4px) x 2 oc-grps (9 oc)
// ==========================================================================
__global__ __launch_bounds__(240, 2) void k_flows(
    const float* __restrict__ flows_w, const float* __restrict__ flows_b)
{
    __shared__ float sp[8][8*124];    // 31.7 KB
    __shared__ float ws[8*25*18];     // [(ic*25+t)*18 + oc]

    int b   = blockIdx.y;
    int ty0 = blockIdx.x * 4;
    int tid = threadIdx.x;
    int ocg = tid / 120;              // 0..1
    int pt  = tid % 120;
    int r   = pt / 30;                // 0..3
    int cq  = (pt % 30) * 4;          // 0..116
    int o0  = ocg * 9;

    float acc[9][4];
#pragma unroll
    for (int k = 0; k < 9; k++)
#pragma unroll
        for (int j = 0; j < 4; j++) acc[k][j] = 0.f;

    for (int chunk = 0; chunk < 4; chunk++) {
        __syncthreads();
        const float* src = g_f + ((size_t)b*32 + chunk*8)*HW;
        for (int idx = tid; idx < 8*992; idx += 240) {
            int ch = idx / 992, rem = idx % 992;
            int row = rem / 124, col = rem % 124;
            int gy = ty0 - 2 + row, gx = col - 2;
            float v = 0.f;
            if (gy >= 0 && gy < HH && gx >= 0 && gx < WW)
                v = src[(size_t)ch*HW + gy*WW + gx];
            sp[ch][row*124 + col] = v;
        }
        for (int idx = tid; idx < 3600; idx += 240) {
            int oc = idx % 18, rest = idx / 18;
            int ic = rest / 25, t = rest % 25;
            ws[idx] = flows_w[(size_t)oc*(32*25) + (chunk*8 + ic)*25 + t];
        }
        __syncthreads();

#pragma unroll 2
        for (int ic = 0; ic < 8; ic++) {
            float pr[5][8];
#pragma unroll
            for (int dy = 0; dy < 5; dy++) {
                float4 a = *(const float4*)&sp[ic][(r+dy)*124 + cq];
                float4 bb = *(const float4*)&sp[ic][(r+dy)*124 + cq + 4];
                pr[dy][0]=a.x; pr[dy][1]=a.y; pr[dy][2]=a.z; pr[dy][3]=a.w;
                pr[dy][4]=bb.x; pr[dy][5]=bb.y; pr[dy][6]=bb.z; pr[dy][7]=bb.w;
            }
#pragma unroll
            for (int t = 0; t < 25; t++) {
                int dy = t / 5, dx = t % 5;
                const float* wb = &ws[(ic*25 + t)*18 + o0];
#pragma unroll
                for (int k = 0; k < 9; k++) {
                    float w = wb[k];
#pragma unroll
                    for (int j = 0; j < 4; j++)
                        acc[k][j] += w * pr[dy][dx + j];
                }
            }
        }
    }

#pragma unroll
    for (int k = 0; k < 9; k++) {
        float bias = __ldg(&flows_b[o0+k]);
        float4 o;
        o.x = acc[k][0] + bias; o.y = acc[k][1] + bias;
        o.z = acc[k][2] + bias; o.w = acc[k][3] + bias;
        *(float4*)&g_flows[((size_t)b*(2*LNK) + o0 + k)*HW + (ty0+r)*WW + cq] = o;
    }
}

// ==========================================================================
// i2h = conv3x3(x; i2h_w): 8 ch -> 192.
// tile 4 rows x 60 cols. threads 240 = 60 px-threads (4px) x 4 oc-grps.
// 3 oc passes of 64 (16 oc per thread per pass). patches staged once.
// ==========================================================================
__global__ __launch_bounds__(240, 2) void k_i2h(
    const float* __restrict__ x,
    const float* __restrict__ i2h_w, const float* __restrict__ i2h_b)
{
    __shared__ float sp[8][6*64];     // 12.3 KB (cols 0..61 valid, 62/63 zero)
    __shared__ float ws[72*64];       // [(ic*9+t)*64 + oc]  18.4 KB

    int b   = blockIdx.z;
    int ty0 = blockIdx.y * 4;
    int c0  = blockIdx.x * 60;
    int tid = threadIdx.x;
    int ocg = tid / 60;               // 0..3
    int pt  = tid % 60;
    int r   = pt / 15;
    int cq  = (pt % 15) * 4;
    int o0g = ocg * 16;

    for (int idx = tid; idx < 8*384; idx += 240) {
        int ch = idx / 384, rem = idx % 384;
        int row = rem >> 6, col = rem & 63;
        int gy = ty0 - 1 + row, gx = c0 - 1 + col;
        float v = 0.f;
        if (gy >= 0 && gy < HH && gx >= 0 && gx < WW)
            v = x[((size_t)b*NCIN + ch)*HW + gy*WW + gx];
        sp[ch][row*64 + col] = v;
    }

    for (int p = 0; p < 3; p++) {
        int ocbase = p * 64;
        __syncthreads();
        for (int idx = tid; idx < 72*64; idx += 240) {
            int oc = idx & 63, rest = idx >> 6;       // rest = ic*9+t
            ws[rest*64 + oc] = i2h_w[(size_t)(ocbase + oc)*72 + rest];
        }
        __syncthreads();

        float acc[16][4];
#pragma unroll
        for (int k = 0; k < 16; k++)
#pragma unroll
            for (int j = 0; j < 4; j++) acc[k][j] = 0.f;

#pragma unroll 2
        for (int ic = 0; ic < 8; ic++) {
            float pr[3][8];
#pragma unroll
            for (int dy = 0; dy < 3; dy++) {
                float4 a = *(const float4*)&sp[ic][(r+dy)*64 + cq];
                float4 bb = *(const float4*)&sp[ic][(r+dy)*64 + cq + 4];
                pr[dy][0]=a.x; pr[dy][1]=a.y; pr[dy][2]=a.z; pr[dy][3]=a.w;
                pr[dy][4]=bb.x; pr[dy][5]=bb.y; pr[dy][6]=bb.z; pr[dy][7]=bb.w;
            }
#pragma unroll
            for (int t = 0; t < 9; t++) {
                int dy = t / 3, dx = t % 3;
                const float* wb = &ws[(ic*9 + t)*64 + o0g];
                float4 w0 = *(const float4*)wb;
                float4 w1 = *(const float4*)(wb + 4);
                float4 w2 = *(const float4*)(wb + 8);
                float4 w3 = *(const float4*)(wb + 12);
                float wv[16] = {w0.x,w0.y,w0.z,w0.w, w1.x,w1.y,w1.z,w1.w,
                                w2.x,w2.y,w2.z,w2.w, w3.x,w3.y,w3.z,w3.w};
#pragma unroll
                for (int k = 0; k < 16; k++)
#pragma unroll
                    for (int j = 0; j < 4; j++)
                        acc[k][j] += wv[k] * pr[dy][dx + j];
            }
        }

#pragma unroll
        for (int k = 0; k < 16; k++) {
            int oc = ocbase + o0g + k;
            float bias = __ldg(&i2h_b[oc]);
            float4 o;
            o.x = acc[k][0] + bias; o.y = acc[k][1] + bias;
            o.z = acc[k][2] + bias; o.w = acc[k][3] + bias;
            *(float4*)&g_i2h[((size_t)b*C3 + oc)*HW + (ty0+r)*WW + c0 + cq] = o;
        }
    }
}

// ---------------- fused warp(x9) + 1x1 conv + GRU gates -------------------
#define SW_STRIDE 193
#define SO_STRIDE 65
#define SMEM_MAIN_FLOATS (12480 + 4096 + 128)

__global__ __launch_bounds__(256) void k_main(
    const float* __restrict__ hp,
    const float* __restrict__ h2h_w, const float* __restrict__ h2h_b,
    float* __restrict__ out)
{
    extern __shared__ float sm[];
    float* swt = sm;                 // weights [c][o] stride 193; epilogue [o][px] stride 65
    float* wsh = sm + 12480;         // warped  [c][px]  64x64
    float* fsh = sm + 12480 + 4096;  // flow sx/sy per px (2x64)

    int b   = blockIdx.y;
    int p0  = blockIdx.x * 64;
    int tid = threadIdx.x;
    int og = tid >> 3, pg = tid & 7;
    int o0 = og * 6;

    float acc[6][8];
#pragma unroll
    for (int k = 0; k < 6; k++)
#pragma unroll
        for (int j = 0; j < 8; j++) acc[k][j] = 0.f;

    const float4* hT4 = g_hT4 + (size_t)b*HW*16;

    for (int l = 0; l < LNK; l++) {
        if (tid < 64) {
            fsh[tid]      = g_flows[((size_t)b*(2*LNK) + 2*l    )*HW + p0 + tid];
            fsh[64 + tid] = g_flows[((size_t)b*(2*LNK) + 2*l + 1)*HW + p0 + tid];
        }
#pragma unroll 4
        for (int idx = tid; idx < 12288; idx += 256) {
            int o = idx >> 6, c = idx & 63;
            swt[c*SW_STRIDE + o] = h2h_w[(size_t)o*576 + l*64 + c];
        }
        __syncthreads();

#pragma unroll
        for (int it = 0; it < 4; it++) {
            int item = it*256 + tid;
            int px = item & 63, cg = item >> 6;
            int p = p0 + px;
            int yc = p / WW, xc = p - yc*WW;
            float sx = (float)xc + fsh[px];
            float sy = (float)yc + fsh[64 + px];
            float fx = floorf(sx), fy = floorf(sy);
            float wx1 = sx - fx, wy1 = sy - fy;
            float wx0 = 1.f - wx1, wy0 = 1.f - wy1;
            int ix0 = (int)fx, iy0 = (int)fy;
            bool vx0 = (ix0 >= 0) && (ix0 < WW);
            bool vx1 = (ix0 >= -1) && (ix0 < WW - 1);
            bool vy0 = (iy0 >= 0) && (iy0 < HH);
            bool vy1 = (iy0 >= -1) && (iy0 < HH - 1);
            float4 z = make_float4(0.f, 0.f, 0.f, 0.f);
            float4 v00 = z, v01 = z, v10 = z, v11 = z;
            if (vy0) {
                int rb = iy0 * WW;
                if (vx0) v00 = hT4[(size_t)(rb + ix0    )*16 + cg];
                if (vx1) v01 = hT4[(size_t)(rb + ix0 + 1)*16 + cg];
            }
            if (vy1) {
                int rb = (iy0 + 1) * WW;
                if (vx0) v10 = hT4[(size_t)(rb + ix0    )*16 + cg];
                if (vx1) v11 = hT4[(size_t)(rb + ix0 + 1)*16 + cg];
            }
            float w00 = wy0*wx0, w01 = wy0*wx1, w10 = wy1*wx0, w11 = wy1*wx1;
            int cb = cg * 4;
            wsh[(cb    )*64 + px] = w00*v00.x + w01*v01.x + w10*v10.x + w11*v11.x;
            wsh[(cb + 1)*64 + px] = w00*v00.y + w01*v01.y + w10*v10.y + w11*v11.y;
            wsh[(cb + 2)*64 + px] = w00*v00.z + w01*v01.z + w10*v10.z + w11*v11.z;
            wsh[(cb + 3)*64 + px] = w00*v00.w + w01*v01.w + w10*v10.w + w11*v11.w;
        }
        __syncthreads();

#pragma unroll 2
        for (int c = 0; c < 64; c++) {
            float4 va = *(const float4*)&wsh[c*64 + pg*8];
            float4 vb = *(const float4*)&wsh[c*64 + pg*8 + 4];
#pragma unroll
            for (int k = 0; k < 6; k++) {
                float w = swt[c*SW_STRIDE + o0 + k];
                acc[k][0] += w * va.x;  acc[k][1] += w * va.y;
                acc[k][2] += w * va.z;  acc[k][3] += w * va.w;
                acc[k][4] += w * vb.x;  acc[k][5] += w * vb.y;
                acc[k][6] += w * vb.z;  acc[k][7] += w * vb.w;
            }
        }
        __syncthreads();
    }

#pragma unroll
    for (int k = 0; k < 6; k++) {
        float bias = __ldg(&h2h_b[o0 + k]);
#pragma unroll
        for (int j = 0; j < 8; j++)
            swt[(o0 + k)*SO_STRIDE + pg*8 + j] = acc[k][j] + bias;
    }
    __syncthreads();

    const float* i2hb = g_i2h + (size_t)b*C3*HW;
#pragma unroll
    for (int k = 0; k < 16; k++) {
        int idx = k*256 + tid;
        int c = idx >> 6, px = idx & 63;
        int p = p0 + px;
        float hr = swt[(c      )*SO_STRIDE + px];
        float hu = swt[(c +  64)*SO_STRIDE + px];
        float hm = swt[(c + 128)*SO_STRIDE + px];
        float ir = i2hb[(size_t)(c      )*HW + p];
        float iu = i2hb[(size_t)(c +  64)*HW + p];
        float im = i2hb[(size_t)(c + 128)*HW + p];
        float hpv = hp[((size_t)b*HID + c)*HW + p];
        float rg = 1.f / (1.f + expf(-(ir + hr)));
        float ug = 1.f / (1.f + expf(-(iu + hu)));
        float nm = tanhf(im + rg * hm);
        out[((size_t)b*HID + c)*HW + p] = ug * hpv + (1.f - ug) * nm;
    }
}

// ---------------- launch ---------------------------------------------------
extern "C" void kernel_launch(void* const* d_in, const int* in_sizes, int n_in,
                              void* d_out, int out_size)
{
    const float* x       = (const float*)d_in[0];
    const float* h_prev  = (const float*)d_in[1];
    const float* i2h_w   = (const float*)d_in[2];
    const float* i2h_b   = (const float*)d_in[3];
    const float* h2h_w   = (const float*)d_in[4];
    const float* h2h_b   = (const float*)d_in[5];
    const float* i2f_w   = (const float*)d_in[6];
    const float* i2f_b   = (const float*)d_in[7];
    const float* h2f_w   = (const float*)d_in[8];
    const float* h2f_b   = (const float*)d_in[9];
    const float* flows_w = (const float*)d_in[10];
    const float* flows_b = (const float*)d_in[11];
    float* out = (float*)d_out;

    cudaFuncSetAttribute(k_main, cudaFuncAttributeMaxDynamicSharedMemorySize,
                         SMEM_MAIN_FLOATS * (int)sizeof(float));

    dim3 gt(HW/32, HID/32, BATCH);
    k_transpose<<<gt, dim3(32, 8)>>>(h_prev);

    dim3 gf(2, 30, BATCH);
    k_f<<<gf, 240>>>(x, h_prev, i2f_w, i2f_b, h2f_w, h2f_b);
    k_i2h<<<gf, 240>>>(x, i2h_w, i2h_b);

    dim3 gfl(30, BATCH);
    k_flows<<<gfl, 240>>>(flows_w, flows_b);

    dim3 gm(HW/64, BATCH);
    k_main<<<gm, 256, SMEM_MAIN_FLOATS * (int)sizeof(float)>>>(h_prev, h2h_w, h2h_b, out);
}

// round 3
// speedup vs baseline: 1.4678x; 1.1434x over previous
#include <cuda_runtime.h>
#include <math.h>

#define BATCH 8
#define NCIN 8
#define HID 64
#define LNK 9
#define HH 120
#define WW 120
#define HW (HH*WW)      // 14400
#define C3 (3*HID)      // 192

typedef unsigned long long ull;

__device__ __forceinline__ ull pack2(float a, float b) {
    ull r; asm("mov.b64 %0, {%1,%2};" : "=l"(r) : "f"(a), "f"(b)); return r;
}
__device__ __forceinline__ ull bcast2(float a) { return pack2(a, a); }
__device__ __forceinline__ void fma2(ull& d, ull a, ull b) {
    asm("fma.rn.f32x2 %0, %1, %2, %0;" : "+l"(d) : "l"(a), "l"(b));
}
__device__ __forceinline__ float2 unpack2(ull v) {
    float2 r; asm("mov.b64 {%0,%1}, %2;" : "=f"(r.x), "=f"(r.y) : "l"(v)); return r;
}

// -------- scratch (device globals; no allocation in kernel_launch) --------
__device__ float  g_f[BATCH*32*HW];
__device__ float  g_flows[BATCH*2*LNK*HW];
__device__ float  g_i2h[(size_t)BATCH*C3*HW];
__device__ float4 g_hT4[(size_t)BATCH*HW*16];   // h_prev as [b][p][c]

// ---------------- transpose h_prev NCHW -> NHWC ---------------------------
__global__ void k_transpose(const float* __restrict__ hp)
{
    __shared__ float t[32][33];
    int b  = blockIdx.z;
    int c0 = blockIdx.y * 32;
    int p0 = blockIdx.x * 32;
    int tx = threadIdx.x, ty = threadIdx.y;
    float* hT = (float*)g_hT4;
#pragma unroll
    for (int k = 0; k < 4; k++) {
        int c = c0 + ty + k*8;
        t[ty + k*8][tx] = hp[((size_t)b*HID + c)*HW + p0 + tx];
    }
    __syncthreads();
#pragma unroll
    for (int k = 0; k < 4; k++) {
        int p = p0 + ty + k*8;
        hT[((size_t)b*HW + p)*HID + c0 + tx] = t[tx][ty + k*8];
    }
}

// ==========================================================================
// f = relu(conv5x5(x;i2f) + conv5x5(h_prev;h2f))  -- f32x2, oc-packed
// ==========================================================================
__global__ __launch_bounds__(240, 2) void k_f(
    const float* __restrict__ x, const float* __restrict__ hp,
    const float* __restrict__ i2f_w, const float* __restrict__ i2f_b,
    const float* __restrict__ h2f_w, const float* __restrict__ h2f_b)
{
    __shared__ float sp[8][8*68];
    __shared__ float ws[8*25*32];     // [(ic*25+t)*32 + oc]

    int b   = blockIdx.z;
    int ty0 = blockIdx.y * 4;
    int c0  = blockIdx.x * 60;
    int tid = threadIdx.x;
    int ocg = tid / 60;
    int pt  = tid % 60;
    int r   = pt / 15;
    int cq  = (pt % 15) * 4;
    int o0  = ocg * 8;

    ull acc2[4][4];                   // [oc-pair][px]
#pragma unroll
    for (int p = 0; p < 4; p++)
#pragma unroll
        for (int j = 0; j < 4; j++) acc2[p][j] = 0ull;

    for (int chunk = 0; chunk < 9; chunk++) {
        __syncthreads();
        const float* src = (chunk == 0) ? (x + (size_t)b*NCIN*HW)
                                        : (hp + ((size_t)b*HID + (chunk-1)*8)*HW);
        for (int idx = tid; idx < 8*512; idx += 240) {
            int ch = idx >> 9, rem = idx & 511;
            int row = rem >> 6, col = rem & 63;
            int gy = ty0 - 2 + row, gx = c0 - 2 + col;
            float v = 0.f;
            if (gy >= 0 && gy < HH && gx >= 0 && gx < WW)
                v = src[(size_t)ch*HW + gy*WW + gx];
            sp[ch][row*68 + col] = v;
        }
        for (int idx = tid; idx < 6400; idx += 240) {
            int oc = idx & 31, rest = idx >> 5;
            int ic = rest / 25, t = rest % 25;
            float v;
            if (chunk == 0) v = i2f_w[(size_t)oc*(NCIN*25) + ic*25 + t];
            else            v = h2f_w[(size_t)oc*(HID*25) + ((chunk-1)*8 + ic)*25 + t];
            ws[idx] = v;
        }
        __syncthreads();

#pragma unroll 2
        for (int ic = 0; ic < 8; ic++) {
            float pr[5][8];
#pragma unroll
            for (int dy = 0; dy < 5; dy++) {
                float4 a = *(const float4*)&sp[ic][(r+dy)*68 + cq];
                float4 bb = *(const float4*)&sp[ic][(r+dy)*68 + cq + 4];
                pr[dy][0]=a.x; pr[dy][1]=a.y; pr[dy][2]=a.z; pr[dy][3]=a.w;
                pr[dy][4]=bb.x; pr[dy][5]=bb.y; pr[dy][6]=bb.z; pr[dy][7]=bb.w;
            }
#pragma unroll
            for (int t = 0; t < 25; t++) {
                int dy = t / 5, dx = t % 5;
                const ulonglong2* wp = (const ulonglong2*)&ws[(ic*25 + t)*32 + o0];
                ulonglong2 wA = wp[0], wB = wp[1];
                ull w2[4] = {wA.x, wA.y, wB.x, wB.y};
#pragma unroll
                for (int j = 0; j < 4; j++) {
                    ull pb = bcast2(pr[dy][dx + j]);
                    fma2(acc2[0][j], w2[0], pb);
                    fma2(acc2[1][j], w2[1], pb);
                    fma2(acc2[2][j], w2[2], pb);
                    fma2(acc2[3][j], w2[3], pb);
                }
            }
        }
    }

#pragma unroll
    for (int p = 0; p < 4; p++) {
        float2 v0 = unpack2(acc2[p][0]);
        float2 v1 = unpack2(acc2[p][1]);
        float2 v2 = unpack2(acc2[p][2]);
        float2 v3 = unpack2(acc2[p][3]);
        int ocA = o0 + 2*p, ocB = ocA + 1;
        float bA = __ldg(&i2f_b[ocA]) + __ldg(&h2f_b[ocA]);
        float bB = __ldg(&i2f_b[ocB]) + __ldg(&h2f_b[ocB]);
        float4 oA, oB;
        oA.x = fmaxf(v0.x + bA, 0.f); oA.y = fmaxf(v1.x + bA, 0.f);
        oA.z = fmaxf(v2.x + bA, 0.f); oA.w = fmaxf(v3.x + bA, 0.f);
        oB.x = fmaxf(v0.y + bB, 0.f); oB.y = fmaxf(v1.y + bB, 0.f);
        oB.z = fmaxf(v2.y + bB, 0.f); oB.w = fmaxf(v3.y + bB, 0.f);
        size_t base = (ty0+r)*WW + c0 + cq;
        *(float4*)&g_f[((size_t)b*32 + ocA)*HW + base] = oA;
        *(float4*)&g_f[((size_t)b*32 + ocB)*HW + base] = oB;
    }
}

// ==========================================================================
// flows = conv5x5(f; flows_w): 32 ch -> 18 -- f32x2, oc-packed (stride 20)
// ==========================================================================
__global__ __launch_bounds__(240, 2) void k_flows(
    const float* __restrict__ flows_w, const float* __restrict__ flows_b)
{
    __shared__ float sp[8][8*124];
    __shared__ float ws[8*25*20];     // slot = oc + (oc>=9), per-t stride 20

    int b   = blockIdx.y;
    int ty0 = blockIdx.x * 4;
    int tid = threadIdx.x;
    int ocg = tid / 120;
    int pt  = tid % 120;
    int r   = pt / 30;
    int cq  = (pt % 30) * 4;
    int o0  = ocg * 9;                // global oc base
    int o0s = ocg * 10;               // shared slot base

    ull acc2[4][4];
    float acc8[4];
#pragma unroll
    for (int p = 0; p < 4; p++) {
        acc8[p] = 0.f;
#pragma unroll
        for (int j = 0; j < 4; j++) acc2[p][j] = 0ull;
    }

    for (int chunk = 0; chunk < 4; chunk++) {
        __syncthreads();
        const float* src = g_f + ((size_t)b*32 + chunk*8)*HW;
        for (int idx = tid; idx < 8*992; idx += 240) {
            int ch = idx / 992, rem = idx % 992;
            int row = rem / 124, col = rem % 124;
            int gy = ty0 - 2 + row, gx = col - 2;
            float v = 0.f;
            if (gy >= 0 && gy < HH && gx >= 0 && gx < WW)
                v = src[(size_t)ch*HW + gy*WW + gx];
            sp[ch][row*124 + col] = v;
        }
        for (int idx = tid; idx < 3600; idx += 240) {
            int oc = idx % 18, rest = idx / 18;   // rest = ic*25+t
            int ic = rest / 25, t = rest % 25;
            int slot = oc + (oc >= 9 ? 1 : 0);
            ws[rest*20 + slot] = flows_w[(size_t)oc*(32*25) + (chunk*8 + ic)*25 + t];
        }
        __syncthreads();

#pragma unroll 2
        for (int ic = 0; ic < 8; ic++) {
            float pr[5][8];
#pragma unroll
            for (int dy = 0; dy < 5; dy++) {
                float4 a = *(const float4*)&sp[ic][(r+dy)*124 + cq];
                float4 bb = *(const float4*)&sp[ic][(r+dy)*124 + cq + 4];
                pr[dy][0]=a.x; pr[dy][1]=a.y; pr[dy][2]=a.z; pr[dy][3]=a.w;
                pr[dy][4]=bb.x; pr[dy][5]=bb.y; pr[dy][6]=bb.z; pr[dy][7]=bb.w;
            }
#pragma unroll
            for (int t = 0; t < 25; t++) {
                int dy = t / 5, dx = t % 5;
                const ull* wp = (const ull*)&ws[(ic*25 + t)*20 + o0s];
                ull w2[4] = {wp[0], wp[1], wp[2], wp[3]};
                float w8 = ws[(ic*25 + t)*20 + o0s + 8];
#pragma unroll
                for (int j = 0; j < 4; j++) {
                    float pv = pr[dy][dx + j];
                    ull pb = bcast2(pv);
                    fma2(acc2[0][j], w2[0], pb);
                    fma2(acc2[1][j], w2[1], pb);
                    fma2(acc2[2][j], w2[2], pb);
                    fma2(acc2[3][j], w2[3], pb);
                    acc8[j] += w8 * pv;
                }
            }
        }
    }

    size_t base = (ty0+r)*WW + cq;
#pragma unroll
    for (int p = 0; p < 4; p++) {
        float2 v0 = unpack2(acc2[p][0]);
        float2 v1 = unpack2(acc2[p][1]);
        float2 v2 = unpack2(acc2[p][2]);
        float2 v3 = unpack2(acc2[p][3]);
        int ocA = o0 + 2*p, ocB = ocA + 1;
        float bA = __ldg(&flows_b[ocA]);
        float bB = __ldg(&flows_b[ocB]);
        float4 oA, oB;
        oA.x = v0.x + bA; oA.y = v1.x + bA; oA.z = v2.x + bA; oA.w = v3.x + bA;
        oB.x = v0.y + bB; oB.y = v1.y + bB; oB.z = v2.y + bB; oB.w = v3.y + bB;
        *(float4*)&g_flows[((size_t)b*(2*LNK) + ocA)*HW + base] = oA;
        *(float4*)&g_flows[((size_t)b*(2*LNK) + ocB)*HW + base] = oB;
    }
    {
        int oc = o0 + 8;
        float bias = __ldg(&flows_b[oc]);
        float4 o;
        o.x = acc8[0] + bias; o.y = acc8[1] + bias;
        o.z = acc8[2] + bias; o.w = acc8[3] + bias;
        *(float4*)&g_flows[((size_t)b*(2*LNK) + oc)*HW + base] = o;
    }
}

// ==========================================================================
// i2h = conv3x3(x; i2h_w): 8 ch -> 192 -- f32x2, oc-packed
// ==========================================================================
__global__ __launch_bounds__(240, 2) void k_i2h(
    const float* __restrict__ x,
    const float* __restrict__ i2h_w, const float* __restrict__ i2h_b)
{
    __shared__ float sp[8][6*64];
    __shared__ float ws[72*64];       // [(ic*9+t)*64 + oc]

    int b   = blockIdx.z;
    int ty0 = blockIdx.y * 4;
    int c0  = blockIdx.x * 60;
    int tid = threadIdx.x;
    int ocg = tid / 60;
    int pt  = tid % 60;
    int r   = pt / 15;
    int cq  = (pt % 15) * 4;
    int o0g = ocg * 16;

    for (int idx = tid; idx < 8*384; idx += 240) {
        int ch = idx / 384, rem = idx % 384;
        int row = rem >> 6, col = rem & 63;
        int gy = ty0 - 1 + row, gx = c0 - 1 + col;
        float v = 0.f;
        if (gy >= 0 && gy < HH && gx >= 0 && gx < WW)
            v = x[((size_t)b*NCIN + ch)*HW + gy*WW + gx];
        sp[ch][row*64 + col] = v;
    }

    for (int p = 0; p < 3; p++) {
        int ocbase = p * 64;
        __syncthreads();
        for (int idx = tid; idx < 72*64; idx += 240) {
            int oc = idx & 63, rest = idx >> 6;
            ws[rest*64 + oc] = i2h_w[(size_t)(ocbase + oc)*72 + rest];
        }
        __syncthreads();

        ull acc2[8][4];
#pragma unroll
        for (int k = 0; k < 8; k++)
#pragma unroll
            for (int j = 0; j < 4; j++) acc2[k][j] = 0ull;

#pragma unroll 2
        for (int ic = 0; ic < 8; ic++) {
            float pr[3][8];
#pragma unroll
            for (int dy = 0; dy < 3; dy++) {
                float4 a = *(const float4*)&sp[ic][(r+dy)*64 + cq];
                float4 bb = *(const float4*)&sp[ic][(r+dy)*64 + cq + 4];
                pr[dy][0]=a.x; pr[dy][1]=a.y; pr[dy][2]=a.z; pr[dy][3]=a.w;
                pr[dy][4]=bb.x; pr[dy][5]=bb.y; pr[dy][6]=bb.z; pr[dy][7]=bb.w;
            }
#pragma unroll
            for (int t = 0; t < 9; t++) {
                int dy = t / 3, dx = t % 3;
                const ulonglong2* wp = (const ulonglong2*)&ws[(ic*9 + t)*64 + o0g];
                ulonglong2 wA = wp[0], wB = wp[1], wC = wp[2], wD = wp[3];
                ull w2[8] = {wA.x, wA.y, wB.x, wB.y, wC.x, wC.y, wD.x, wD.y};
#pragma unroll
                for (int j = 0; j < 4; j++) {
                    ull pb = bcast2(pr[dy][dx + j]);
#pragma unroll
                    for (int k = 0; k < 8; k++)
                        fma2(acc2[k][j], w2[k], pb);
                }
            }
        }

        size_t base = (ty0+r)*WW + c0 + cq;
#pragma unroll
        for (int k = 0; k < 8; k++) {
            float2 v0 = unpack2(acc2[k][0]);
            float2 v1 = unpack2(acc2[k][1]);
            float2 v2 = unpack2(acc2[k][2]);
            float2 v3 = unpack2(acc2[k][3]);
            int ocA = ocbase + o0g + 2*k, ocB = ocA + 1;
            float bA = __ldg(&i2h_b[ocA]);
            float bB = __ldg(&i2h_b[ocB]);
            float4 oA, oB;
            oA.x = v0.x + bA; oA.y = v1.x + bA; oA.z = v2.x + bA; oA.w = v3.x + bA;
            oB.x = v0.y + bB; oB.y = v1.y + bB; oB.z = v2.y + bB; oB.w = v3.y + bB;
            *(float4*)&g_i2h[((size_t)b*C3 + ocA)*HW + base] = oA;
            *(float4*)&g_i2h[((size_t)b*C3 + ocB)*HW + base] = oB;
        }
        __syncthreads();
    }
}

// ---------------- fused warp(x9) + 1x1 conv + GRU gates -------------------
// swt layout: [o][68] (c contiguous)  -> vectorized staging from h2h_w
// wsh layout: [c][64] (px contiguous) -> natural px-pair ull operands
#define SWT_STRIDE 68
#define SO_STRIDE 65
#define SMEM_MAIN_FLOATS (192*SWT_STRIDE + 4096 + 128)

__global__ __launch_bounds__(256, 2) void k_main(
    const float* __restrict__ hp,
    const float* __restrict__ h2h_w, const float* __restrict__ h2h_b,
    float* __restrict__ out)
{
    extern __shared__ float sm[];
    float* swt = sm;                       // 13056 floats
    float* wsh = sm + 192*SWT_STRIDE;      // 4096
    float* fsh = sm + 192*SWT_STRIDE + 4096;

    int b   = blockIdx.y;
    int p0  = blockIdx.x * 64;
    int tid = threadIdx.x;
    int og = tid >> 3, pg = tid & 7;
    int o0 = og * 6;

    ull acc2[6][4];
#pragma unroll
    for (int k = 0; k < 6; k++)
#pragma unroll
        for (int j = 0; j < 4; j++) acc2[k][j] = 0ull;

    const float4* hT4 = g_hT4 + (size_t)b*HW*16;

    for (int l = 0; l < LNK; l++) {
        if (tid < 64) {
            fsh[tid]      = g_flows[((size_t)b*(2*LNK) + 2*l    )*HW + p0 + tid];
            fsh[64 + tid] = g_flows[((size_t)b*(2*LNK) + 2*l + 1)*HW + p0 + tid];
        }
        // stage weights: contiguous copy, [o][c]
#pragma unroll
        for (int it = 0; it < 12; it++) {
            int idx = it*256 + tid;            // 0..3071 float4s
            int o = idx >> 4, q = idx & 15;
            ((float4*)&swt[o*SWT_STRIDE])[q] =
                ((const float4*)&h2h_w[(size_t)o*576 + l*64])[q];
        }
        __syncthreads();

        // gather warped tile
#pragma unroll
        for (int it = 0; it < 4; it++) {
            int item = it*256 + tid;
            int px = item & 63, cg = item >> 6;
            int p = p0 + px;
            int yc = p / WW, xc = p - yc*WW;
            float sx = (float)xc + fsh[px];
            float sy = (float)yc + fsh[64 + px];
            float fx = floorf(sx), fy = floorf(sy);
            float wx1 = sx - fx, wy1 = sy - fy;
            float wx0 = 1.f - wx1, wy0 = 1.f - wy1;
            int ix0 = (int)fx, iy0 = (int)fy;
            bool vx0 = (ix0 >= 0) && (ix0 < WW);
            bool vx1 = (ix0 >= -1) && (ix0 < WW - 1);
            bool vy0 = (iy0 >= 0) && (iy0 < HH);
            bool vy1 = (iy0 >= -1) && (iy0 < HH - 1);
            float4 z = make_float4(0.f, 0.f, 0.f, 0.f);
            float4 v00 = z, v01 = z, v10 = z, v11 = z;
            if (vy0) {
                int rb = iy0 * WW;
                if (vx0) v00 = hT4[(size_t)(rb + ix0    )*16 + cg];
                if (vx1) v01 = hT4[(size_t)(rb + ix0 + 1)*16 + cg];
            }
            if (vy1) {
                int rb = (iy0 + 1) * WW;
                if (vx0) v10 = hT4[(size_t)(rb + ix0    )*16 + cg];
                if (vx1) v11 = hT4[(size_t)(rb + ix0 + 1)*16 + cg];
            }
            float w00 = wy0*wx0, w01 = wy0*wx1, w10 = wy1*wx0, w11 = wy1*wx1;
            int cb = cg * 4;
            wsh[(cb    )*64 + px] = w00*v00.x + w01*v01.x + w10*v10.x + w11*v11.x;
            wsh[(cb + 1)*64 + px] = w00*v00.y + w01*v01.y + w10*v10.y + w11*v11.y;
            wsh[(cb + 2)*64 + px] = w00*v00.z + w01*v01.z + w10*v10.z + w11*v11.z;
            wsh[(cb + 3)*64 + px] = w00*v00.w + w01*v01.w + w10*v10.w + w11*v11.w;
        }
        __syncthreads();

#pragma unroll 2
        for (int c = 0; c < 64; c++) {
            const ulonglong2* ap = (const ulonglong2*)&wsh[c*64 + pg*8];
            ulonglong2 aA = ap[0], aB = ap[1];
            ull a2[4] = {aA.x, aA.y, aB.x, aB.y};
#pragma unroll
            for (int k = 0; k < 6; k++) {
                ull wb = bcast2(swt[(o0 + k)*SWT_STRIDE + c]);
                fma2(acc2[k][0], wb, a2[0]);
                fma2(acc2[k][1], wb, a2[1]);
                fma2(acc2[k][2], wb, a2[2]);
                fma2(acc2[k][3], wb, a2[3]);
            }
        }
        __syncthreads();
    }

    // stash h2h (+bias) to shared for gate mixing
#pragma unroll
    for (int k = 0; k < 6; k++) {
        float bias = __ldg(&h2h_b[o0 + k]);
#pragma unroll
        for (int j = 0; j < 4; j++) {
            float2 v = unpack2(acc2[k][j]);
            swt[(o0 + k)*SO_STRIDE + pg*8 + 2*j    ] = v.x + bias;
            swt[(o0 + k)*SO_STRIDE + pg*8 + 2*j + 1] = v.y + bias;
        }
    }
    __syncthreads();

    const float* i2hb = g_i2h + (size_t)b*C3*HW;
#pragma unroll
    for (int k = 0; k < 16; k++) {
        int idx = k*256 + tid;
        int c = idx >> 6, px = idx & 63;
        int p = p0 + px;
        float hr = swt[(c      )*SO_STRIDE + px];
        float hu = swt[(c +  64)*SO_STRIDE + px];
        float hm = swt[(c + 128)*SO_STRIDE + px];
        float ir = i2hb[(size_t)(c      )*HW + p];
        float iu = i2hb[(size_t)(c +  64)*HW + p];
        float im = i2hb[(size_t)(c + 128)*HW + p];
        float hpv = hp[((size_t)b*HID + c)*HW + p];
        float rg = 1.f / (1.f + expf(-(ir + hr)));
        float ug = 1.f / (1.f + expf(-(iu + hu)));
        float nm = tanhf(im + rg * hm);
        out[((size_t)b*HID + c)*HW + p] = ug * hpv + (1.f - ug) * nm;
    }
}

// ---------------- launch ---------------------------------------------------
extern "C" void kernel_launch(void* const* d_in, const int* in_sizes, int n_in,
                              void* d_out, int out_size)
{
    const float* x       = (const float*)d_in[0];
    const float* h_prev  = (const float*)d_in[1];
    const float* i2h_w   = (const float*)d_in[2];
    const float* i2h_b   = (const float*)d_in[3];
    const float* h2h_w   = (const float*)d_in[4];
    const float* h2h_b   = (const float*)d_in[5];
    const float* i2f_w   = (const float*)d_in[6];
    const float* i2f_b   = (const float*)d_in[7];
    const float* h2f_w   = (const float*)d_in[8];
    const float* h2f_b   = (const float*)d_in[9];
    const float* flows_w = (const float*)d_in[10];
    const float* flows_b = (const float*)d_in[11];
    float* out = (float*)d_out;

    cudaFuncSetAttribute(k_main, cudaFuncAttributeMaxDynamicSharedMemorySize,
                         SMEM_MAIN_FLOATS * (int)sizeof(float));

    dim3 gt(HW/32, HID/32, BATCH);
    k_transpose<<<gt, dim3(32, 8)>>>(h_prev);

    dim3 gf(2, 30, BATCH);
    k_f<<<gf, 240>>>(x, h_prev, i2f_w, i2f_b, h2f_w, h2f_b);
    k_i2h<<<gf, 240>>>(x, i2h_w, i2h_b);

    dim3 gfl(30, BATCH);
    k_flows<<<gfl, 240>>>(flows_w, flows_b);

    dim3 gm(HW/64, BATCH);
    k_main<<<gm, 256, SMEM_MAIN_FLOATS * (int)sizeof(float)>>>(h_prev, h2h_w, h2h_b, out);
}

// round 5
// speedup vs baseline: 1.9117x; 1.3024x over previous
#include <cuda_runtime.h>
#include <math.h>
#include <stdint.h>

#define BATCH 8
#define NCIN 8
#define HID 64
#define LNK 9
#define HH 120
#define WW 120
#define HW (HH*WW)      // 14400
#define C3 (3*HID)      // 192

typedef unsigned long long ull;

__device__ __forceinline__ ull pack2(float a, float b) {
    ull r; asm("mov.b64 %0, {%1,%2};" : "=l"(r) : "f"(a), "f"(b)); return r;
}
__device__ __forceinline__ ull bcast2(float a) { return pack2(a, a); }
__device__ __forceinline__ void fma2(ull& d, ull a, ull b) {
    asm("fma.rn.f32x2 %0, %1, %2, %0;" : "+l"(d) : "l"(a), "l"(b));
}
__device__ __forceinline__ float2 unpack2(ull v) {
    float2 r; asm("mov.b64 {%0,%1}, %2;" : "=f"(r.x), "=f"(r.y) : "l"(v)); return r;
}
__device__ __forceinline__ uint32_t f2tf32(float v) {
    uint32_t r; asm("cvt.rna.tf32.f32 %0, %1;" : "=r"(r) : "f"(v)); return r;
}
__device__ __forceinline__ void mma_tf32(float* d,
    uint32_t a0, uint32_t a1, uint32_t a2, uint32_t a3,
    uint32_t b0, uint32_t b1)
{
    asm volatile("mma.sync.aligned.m16n8k8.row.col.f32.tf32.tf32.f32 "
        "{%0,%1,%2,%3}, {%4,%5,%6,%7}, {%8,%9}, {%0,%1,%2,%3};"
        : "+f"(d[0]), "+f"(d[1]), "+f"(d[2]), "+f"(d[3])
        : "r"(a0), "r"(a1), "r"(a2), "r"(a3), "r"(b0), "r"(b1));
}

// -------- scratch (device globals) ----------------------------------------
__device__ float  g_f[BATCH*32*HW];
__device__ float  g_flows[BATCH*2*LNK*HW];
__device__ float  g_i2h[(size_t)BATCH*C3*HW];
__device__ float4 g_hT4[(size_t)BATCH*HW*16];   // h_prev as [b][p][c]

// ---------------- transpose h_prev NCHW -> NHWC ---------------------------
__global__ void k_transpose(const float* __restrict__ hp)
{
    __shared__ float t[32][33];
    int b  = blockIdx.z;
    int c0 = blockIdx.y * 32;
    int p0 = blockIdx.x * 32;
    int tx = threadIdx.x, ty = threadIdx.y;
    float* hT = (float*)g_hT4;
#pragma unroll
    for (int k = 0; k < 4; k++) {
        int c = c0 + ty + k*8;
        t[ty + k*8][tx] = hp[((size_t)b*HID + c)*HW + p0 + tx];
    }
    __syncthreads();
#pragma unroll
    for (int k = 0; k < 4; k++) {
        int p = p0 + ty + k*8;
        hT[((size_t)b*HW + p)*HID + c0 + tx] = t[tx][ty + k*8];
    }
}

// ==========================================================================
// f = relu(conv5x5(x;i2f) + conv5x5(h_prev;h2f))  -- f32x2, oc-packed
// ==========================================================================
__global__ __launch_bounds__(240, 2) void k_f(
    const float* __restrict__ x, const float* __restrict__ hp,
    const float* __restrict__ i2f_w, const float* __restrict__ i2f_b,
    const float* __restrict__ h2f_w, const float* __restrict__ h2f_b)
{
    __shared__ float sp[8][8*68];
    __shared__ float ws[8*25*32];

    int b   = blockIdx.z;
    int ty0 = blockIdx.y * 4;
    int c0  = blockIdx.x * 60;
    int tid = threadIdx.x;
    int ocg = tid / 60;
    int pt  = tid % 60;
    int r   = pt / 15;
    int cq  = (pt % 15) * 4;
    int o0  = ocg * 8;

    ull acc2[4][4];
#pragma unroll
    for (int p = 0; p < 4; p++)
#pragma unroll
        for (int j = 0; j < 4; j++) acc2[p][j] = 0ull;

    for (int chunk = 0; chunk < 9; chunk++) {
        __syncthreads();
        const float* src = (chunk == 0) ? (x + (size_t)b*NCIN*HW)
                                        : (hp + ((size_t)b*HID + (chunk-1)*8)*HW);
        for (int idx = tid; idx < 8*512; idx += 240) {
            int ch = idx >> 9, rem = idx & 511;
            int row = rem >> 6, col = rem & 63;
            int gy = ty0 - 2 + row, gx = c0 - 2 + col;
            float v = 0.f;
            if (gy >= 0 && gy < HH && gx >= 0 && gx < WW)
                v = src[(size_t)ch*HW + gy*WW + gx];
            sp[ch][row*68 + col] = v;
        }
        for (int idx = tid; idx < 6400; idx += 240) {
            int oc = idx & 31, rest = idx >> 5;
            int ic = rest / 25, t = rest % 25;
            float v;
            if (chunk == 0) v = i2f_w[(size_t)oc*(NCIN*25) + ic*25 + t];
            else            v = h2f_w[(size_t)oc*(HID*25) + ((chunk-1)*8 + ic)*25 + t];
            ws[idx] = v;
        }
        __syncthreads();

#pragma unroll 2
        for (int ic = 0; ic < 8; ic++) {
            float pr[5][8];
#pragma unroll
            for (int dy = 0; dy < 5; dy++) {
                float4 a = *(const float4*)&sp[ic][(r+dy)*68 + cq];
                float4 bb = *(const float4*)&sp[ic][(r+dy)*68 + cq + 4];
                pr[dy][0]=a.x; pr[dy][1]=a.y; pr[dy][2]=a.z; pr[dy][3]=a.w;
                pr[dy][4]=bb.x; pr[dy][5]=bb.y; pr[dy][6]=bb.z; pr[dy][7]=bb.w;
            }
#pragma unroll
            for (int t = 0; t < 25; t++) {
                int dy = t / 5, dx = t % 5;
                const ulonglong2* wp = (const ulonglong2*)&ws[(ic*25 + t)*32 + o0];
                ulonglong2 wA = wp[0], wB = wp[1];
                ull w2[4] = {wA.x, wA.y, wB.x, wB.y};
#pragma unroll
                for (int j = 0; j < 4; j++) {
                    ull pb = bcast2(pr[dy][dx + j]);
                    fma2(acc2[0][j], w2[0], pb);
                    fma2(acc2[1][j], w2[1], pb);
                    fma2(acc2[2][j], w2[2], pb);
                    fma2(acc2[3][j], w2[3], pb);
                }
            }
        }
    }

#pragma unroll
    for (int p = 0; p < 4; p++) {
        float2 v0 = unpack2(acc2[p][0]);
        float2 v1 = unpack2(acc2[p][1]);
        float2 v2 = unpack2(acc2[p][2]);
        float2 v3 = unpack2(acc2[p][3]);
        int ocA = o0 + 2*p, ocB = ocA + 1;
        float bA = __ldg(&i2f_b[ocA]) + __ldg(&h2f_b[ocA]);
        float bB = __ldg(&i2f_b[ocB]) + __ldg(&h2f_b[ocB]);
        float4 oA, oB;
        oA.x = fmaxf(v0.x + bA, 0.f); oA.y = fmaxf(v1.x + bA, 0.f);
        oA.z = fmaxf(v2.x + bA, 0.f); oA.w = fmaxf(v3.x + bA, 0.f);
        oB.x = fmaxf(v0.y + bB, 0.f); oB.y = fmaxf(v1.y + bB, 0.f);
        oB.z = fmaxf(v2.y + bB, 0.f); oB.w = fmaxf(v3.y + bB, 0.f);
        size_t base = (ty0+r)*WW + c0 + cq;
        *(float4*)&g_f[((size_t)b*32 + ocA)*HW + base] = oA;
        *(float4*)&g_f[((size_t)b*32 + ocB)*HW + base] = oB;
    }
}

// ==========================================================================
// flows = conv5x5(f; flows_w): 32 ch -> 18 -- f32x2, oc-packed
// ==========================================================================
__global__ __launch_bounds__(240, 2) void k_flows(
    const float* __restrict__ flows_w, const float* __restrict__ flows_b)
{
    __shared__ float sp[8][8*124];
    __shared__ float ws[8*25*20];

    int b   = blockIdx.y;
    int ty0 = blockIdx.x * 4;
    int tid = threadIdx.x;
    int ocg = tid / 120;
    int pt  = tid % 120;
    int r   = pt / 30;
    int cq  = (pt % 30) * 4;
    int o0  = ocg * 9;
    int o0s = ocg * 10;

    ull acc2[4][4];
    float acc8[4];
#pragma unroll
    for (int p = 0; p < 4; p++) {
        acc8[p] = 0.f;
#pragma unroll
        for (int j = 0; j < 4; j++) acc2[p][j] = 0ull;
    }

    for (int chunk = 0; chunk < 4; chunk++) {
        __syncthreads();
        const float* src = g_f + ((size_t)b*32 + chunk*8)*HW;
        for (int idx = tid; idx < 8*992; idx += 240) {
            int ch = idx / 992, rem = idx % 992;
            int row = rem / 124, col = rem % 124;
            int gy = ty0 - 2 + row, gx = col - 2;
            float v = 0.f;
            if (gy >= 0 && gy < HH && gx >= 0 && gx < WW)
                v = src[(size_t)ch*HW + gy*WW + gx];
            sp[ch][row*124 + col] = v;
        }
        for (int idx = tid; idx < 3600; idx += 240) {
            int oc = idx % 18, rest = idx / 18;
            int ic = rest / 25, t = rest % 25;
            int slot = oc + (oc >= 9 ? 1 : 0);
            ws[rest*20 + slot] = flows_w[(size_t)oc*(32*25) + (chunk*8 + ic)*25 + t];
        }
        __syncthreads();

#pragma unroll 2
        for (int ic = 0; ic < 8; ic++) {
            float pr[5][8];
#pragma unroll
            for (int dy = 0; dy < 5; dy++) {
                float4 a = *(const float4*)&sp[ic][(r+dy)*124 + cq];
                float4 bb = *(const float4*)&sp[ic][(r+dy)*124 + cq + 4];
                pr[dy][0]=a.x; pr[dy][1]=a.y; pr[dy][2]=a.z; pr[dy][3]=a.w;
                pr[dy][4]=bb.x; pr[dy][5]=bb.y; pr[dy][6]=bb.z; pr[dy][7]=bb.w;
            }
#pragma unroll
            for (int t = 0; t < 25; t++) {
                int dy = t / 5, dx = t % 5;
                const ull* wp = (const ull*)&ws[(ic*25 + t)*20 + o0s];
                ull w2[4] = {wp[0], wp[1], wp[2], wp[3]};
                float w8 = ws[(ic*25 + t)*20 + o0s + 8];
#pragma unroll
                for (int j = 0; j < 4; j++) {
                    float pv = pr[dy][dx + j];
                    ull pb = bcast2(pv);
                    fma2(acc2[0][j], w2[0], pb);
                    fma2(acc2[1][j], w2[1], pb);
                    fma2(acc2[2][j], w2[2], pb);
                    fma2(acc2[3][j], w2[3], pb);
                    acc8[j] += w8 * pv;
                }
            }
        }
    }

    size_t base = (ty0+r)*WW + cq;
#pragma unroll
    for (int p = 0; p < 4; p++) {
        float2 v0 = unpack2(acc2[p][0]);
        float2 v1 = unpack2(acc2[p][1]);
        float2 v2 = unpack2(acc2[p][2]);
        float2 v3 = unpack2(acc2[p][3]);
        int ocA = o0 + 2*p, ocB = ocA + 1;
        float bA = __ldg(&flows_b[ocA]);
        float bB = __ldg(&flows_b[ocB]);
        float4 oA, oB;
        oA.x = v0.x + bA; oA.y = v1.x + bA; oA.z = v2.x + bA; oA.w = v3.x + bA;
        oB.x = v0.y + bB; oB.y = v1.y + bB; oB.z = v2.y + bB; oB.w = v3.y + bB;
        *(float4*)&g_flows[((size_t)b*(2*LNK) + ocA)*HW + base] = oA;
        *(float4*)&g_flows[((size_t)b*(2*LNK) + ocB)*HW + base] = oB;
    }
    {
        int oc = o0 + 8;
        float bias = __ldg(&flows_b[oc]);
        float4 o;
        o.x = acc8[0] + bias; o.y = acc8[1] + bias;
        o.z = acc8[2] + bias; o.w = acc8[3] + bias;
        *(float4*)&g_flows[((size_t)b*(2*LNK) + oc)*HW + base] = o;
    }
}

// ==========================================================================
// i2h = conv3x3(x; i2h_w): 8 ch -> 192 -- f32x2, oc-packed
// ==========================================================================
__global__ __launch_bounds__(240, 2) void k_i2h(
    const float* __restrict__ x,
    const float* __restrict__ i2h_w, const float* __restrict__ i2h_b)
{
    __shared__ float sp[8][6*64];
    __shared__ float ws[72*64];

    int b   = blockIdx.z;
    int ty0 = blockIdx.y * 4;
    int c0  = blockIdx.x * 60;
    int tid = threadIdx.x;
    int ocg = tid / 60;
    int pt  = tid % 60;
    int r   = pt / 15;
    int cq  = (pt % 15) * 4;
    int o0g = ocg * 16;

    for (int idx = tid; idx < 8*384; idx += 240) {
        int ch = idx / 384, rem = idx % 384;
        int row = rem >> 6, col = rem & 63;
        int gy = ty0 - 1 + row, gx = c0 - 1 + col;
        float v = 0.f;
        if (gy >= 0 && gy < HH && gx >= 0 && gx < WW)
            v = x[((size_t)b*NCIN + ch)*HW + gy*WW + gx];
        sp[ch][row*64 + col] = v;
    }

    for (int p = 0; p < 3; p++) {
        int ocbase = p * 64;
        __syncthreads();
        for (int idx = tid; idx < 72*64; idx += 240) {
            int oc = idx & 63, rest = idx >> 6;
            ws[rest*64 + oc] = i2h_w[(size_t)(ocbase + oc)*72 + rest];
        }
        __syncthreads();

        ull acc2[8][4];
#pragma unroll
        for (int k = 0; k < 8; k++)
#pragma unroll
            for (int j = 0; j < 4; j++) acc2[k][j] = 0ull;

#pragma unroll 2
        for (int ic = 0; ic < 8; ic++) {
            float pr[3][8];
#pragma unroll
            for (int dy = 0; dy < 3; dy++) {
                float4 a = *(const float4*)&sp[ic][(r+dy)*64 + cq];
                float4 bb = *(const float4*)&sp[ic][(r+dy)*64 + cq + 4];
                pr[dy][0]=a.x; pr[dy][1]=a.y; pr[dy][2]=a.z; pr[dy][3]=a.w;
                pr[dy][4]=bb.x; pr[dy][5]=bb.y; pr[dy][6]=bb.z; pr[dy][7]=bb.w;
            }
#pragma unroll
            for (int t = 0; t < 9; t++) {
                int dy = t / 3, dx = t % 3;
                const ulonglong2* wp = (const ulonglong2*)&ws[(ic*9 + t)*64 + o0g];
                ulonglong2 wA = wp[0], wB = wp[1], wC = wp[2], wD = wp[3];
                ull w2[8] = {wA.x, wA.y, wB.x, wB.y, wC.x, wC.y, wD.x, wD.y};
#pragma unroll
                for (int j = 0; j < 4; j++) {
                    ull pb = bcast2(pr[dy][dx + j]);
#pragma unroll
                    for (int k = 0; k < 8; k++)
                        fma2(acc2[k][j], w2[k], pb);
                }
            }
        }

        size_t base = (ty0+r)*WW + c0 + cq;
#pragma unroll
        for (int k = 0; k < 8; k++) {
            float2 v0 = unpack2(acc2[k][0]);
            float2 v1 = unpack2(acc2[k][1]);
            float2 v2 = unpack2(acc2[k][2]);
            float2 v3 = unpack2(acc2[k][3]);
            int ocA = ocbase + o0g + 2*k, ocB = ocA + 1;
            float bA = __ldg(&i2h_b[ocA]);
            float bB = __ldg(&i2h_b[ocB]);
            float4 oA, oB;
            oA.x = v0.x + bA; oA.y = v1.x + bA; oA.z = v2.x + bA; oA.w = v3.x + bA;
            oB.x = v0.y + bB; oB.y = v1.y + bB; oB.z = v2.y + bB; oB.w = v3.y + bB;
            *(float4*)&g_i2h[((size_t)b*C3 + ocA)*HW + base] = oA;
            *(float4*)&g_i2h[((size_t)b*C3 + ocB)*HW + base] = oB;
        }
        __syncthreads();
    }
}

// ==========================================================================
// k_main: fused warp(x9) + 1x1 conv via mma.sync tf32 + GRU gates
// CTA 256 thr (8 warps): 128 px (M) x 192 oc (N), K = 9 links x 64.
// warps: warpM = wid&3 (32 px), warpN = wid>>2 (96 oc).
// sA [128px][72] / sB [192oc][72] hold tf32 bits, k-permuted within each
// k8 block: physical col = (k&3)*2 + (k>>2), so (k, k+4) are adjacent.
// ==========================================================================
#define SA_STRIDE 72
#define SB_STRIDE 72
#define OFF_GEO 0
#define OFF_A   4096
#define OFF_B   (OFF_A + 128*SA_STRIDE*4)          // 40960
#define PHASE1_BYTES (OFF_B + 192*SB_STRIDE*4)     // 96256
#define SD_STRIDE 194
#define SD_BYTES (128*SD_STRIDE*4)                 // 99328
#define SMEM_MMA_BYTES (SD_BYTES > PHASE1_BYTES ? SD_BYTES : PHASE1_BYTES)

__global__ __launch_bounds__(256, 1) void k_main_mma(
    const float* __restrict__ hp,
    const float* __restrict__ h2h_w, const float* __restrict__ h2h_b,
    float* __restrict__ out)
{
    extern __shared__ char sm[];
    float*    sgeo = (float*)(sm + OFF_GEO);          // [128][8]
    uint32_t* sA   = (uint32_t*)(sm + OFF_A);
    uint32_t* sB   = (uint32_t*)(sm + OFF_B);
    float*    sD   = (float*)sm;                      // phase 2 overlay

    int b   = blockIdx.y;
    int p0  = blockIdx.x * 128;
    int tid = threadIdx.x;
    int wid = tid >> 5, lane = tid & 31;
    int warpM = wid & 3, warpN = wid >> 2;
    int lq = lane >> 2, lr = lane & 3;                // quad row / col

    float acc[2][12][4];
#pragma unroll
    for (int mi = 0; mi < 2; mi++)
#pragma unroll
        for (int ni = 0; ni < 12; ni++)
#pragma unroll
            for (int j = 0; j < 4; j++) acc[mi][ni][j] = 0.f;

    const float4* hT4 = g_hT4 + (size_t)b*HW*16;

    for (int l = 0; l < LNK; l++) {
        // --- per-pixel bilinear geometry ---
        if (tid < 128) {
            int p = p0 + tid; if (p > HW-1) p = HW-1;
            int yc = p / WW, xc = p - yc*WW;
            float sx = (float)xc + g_flows[((size_t)b*(2*LNK) + 2*l    )*HW + p];
            float sy = (float)yc + g_flows[((size_t)b*(2*LNK) + 2*l + 1)*HW + p];
            float fx = floorf(sx), fy = floorf(sy);
            float wx1 = sx - fx, wy1 = sy - fy;
            float wx0 = 1.f - wx1, wy0 = 1.f - wy1;
            int ix0 = (int)fx, iy0 = (int)fy;
            bool vx0 = (ix0 >= 0) && (ix0 < WW);
            bool vx1 = (ix0 >= -1) && (ix0 < WW - 1);
            bool vy0 = (iy0 >= 0) && (iy0 < HH);
            bool vy1 = (iy0 >= -1) && (iy0 < HH - 1);
            int r0 = iy0*WW, r1 = r0 + WW;
            float* g = &sgeo[tid*8];
            g[0] = wy0*wx0; g[1] = wy0*wx1; g[2] = wy1*wx0; g[3] = wy1*wx1;
            ((int*)g)[4] = (vy0 && vx0) ? (r0 + ix0)     : -1;
            ((int*)g)[5] = (vy0 && vx1) ? (r0 + ix0 + 1) : -1;
            ((int*)g)[6] = (vy1 && vx0) ? (r1 + ix0)     : -1;
            ((int*)g)[7] = (vy1 && vx1) ? (r1 + ix0 + 1) : -1;
        }
        __syncthreads();

        // --- stage B weights [192][64] -> tf32, k-permuted ---
#pragma unroll
        for (int i = 0; i < 12; i++) {
            int q = i*256 + tid;               // float4 idx 0..3071
            int o = q >> 4, kq = q & 15;       // kq*4 = logical k0
            float4 w = *(const float4*)&h2h_w[(size_t)o*576 + l*64 + kq*4];
            int blk = kq >> 1;                 // k8 block
            int base = o*SB_STRIDE + blk*8 + (kq & 1);   // odd half: k>=4
            sB[base    ] = f2tf32(w.x);
            sB[base + 2] = f2tf32(w.y);
            sB[base + 4] = f2tf32(w.z);
            sB[base + 6] = f2tf32(w.w);
        }

        // --- gather A: warped [128px][64ch] -> tf32, k-permuted ---
#pragma unroll
        for (int i = 0; i < 8; i++) {
            int item = i*256 + tid;            // 0..2047
            int px = item >> 4, cg = item & 15;
            const float* g = &sgeo[px*8];
            float w00 = g[0], w01 = g[1], w10 = g[2], w11 = g[3];
            int i00 = ((const int*)g)[4], i01 = ((const int*)g)[5];
            int i10 = ((const int*)g)[6], i11 = ((const int*)g)[7];
            float ax=0.f, ay=0.f, az=0.f, aw=0.f;
            if (i00 >= 0) { float4 v = hT4[(size_t)i00*16 + cg];
                ax += w00*v.x; ay += w00*v.y; az += w00*v.z; aw += w00*v.w; }
            if (i01 >= 0) { float4 v = hT4[(size_t)i01*16 + cg];
                ax += w01*v.x; ay += w01*v.y; az += w01*v.z; aw += w01*v.w; }
            if (i10 >= 0) { float4 v = hT4[(size_t)i10*16 + cg];
                ax += w10*v.x; ay += w10*v.y; az += w10*v.z; aw += w10*v.w; }
            if (i11 >= 0) { float4 v = hT4[(size_t)i11*16 + cg];
                ax += w11*v.x; ay += w11*v.y; az += w11*v.z; aw += w11*v.w; }
            int blk = cg >> 1;
            int base = px*SA_STRIDE + blk*8 + (cg & 1);
            sA[base    ] = f2tf32(ax);
            sA[base + 2] = f2tf32(ay);
            sA[base + 4] = f2tf32(az);
            sA[base + 6] = f2tf32(aw);
        }
        __syncthreads();

        // --- 8 k-steps of m16n8k8 ---
        const uint32_t* Ab = sA + (warpM*32 + lq)*SA_STRIDE;
        const uint32_t* Bb = sB + (warpN*96 + lq)*SB_STRIDE;
#pragma unroll
        for (int kb = 0; kb < 8; kb++) {
            int col = kb*8 + 2*lr;
            uint2 a00 = *(const uint2*)&Ab[col];                  // rows lq
            uint2 a01 = *(const uint2*)&Ab[8*SA_STRIDE + col];    // rows lq+8
            uint2 a10 = *(const uint2*)&Ab[16*SA_STRIDE + col];
            uint2 a11 = *(const uint2*)&Ab[24*SA_STRIDE + col];
#pragma unroll
            for (int ni = 0; ni < 12; ni++) {
                uint2 bb = *(const uint2*)&Bb[ni*8*SB_STRIDE + col];
                mma_tf32(acc[0][ni], a00.x, a01.x, a00.y, a01.y, bb.x, bb.y);
                mma_tf32(acc[1][ni], a10.x, a11.x, a10.y, a11.y, bb.x, bb.y);
            }
        }
        __syncthreads();
    }

    // --- write fragments to sD [128px][192oc] (overlays sA/sB/sgeo) ---
#pragma unroll
    for (int mi = 0; mi < 2; mi++) {
        int rbase = warpM*32 + mi*16 + lq;
#pragma unroll
        for (int ni = 0; ni < 12; ni++) {
            int cc = warpN*96 + ni*8 + 2*lr;
            *(float2*)&sD[(rbase    )*SD_STRIDE + cc] = make_float2(acc[mi][ni][0], acc[mi][ni][1]);
            *(float2*)&sD[(rbase + 8)*SD_STRIDE + cc] = make_float2(acc[mi][ni][2], acc[mi][ni][3]);
        }
    }
    __syncthreads();

    // --- fused GRU gates ---
    const float* i2hb = g_i2h + (size_t)b*C3*HW;
#pragma unroll
    for (int it = 0; it < 32; it++) {
        int idx = it*256 + tid;               // 64c x 128px
        int c = idx >> 7, px = idx & 127;
        int p = p0 + px;
        if (p < HW) {
            float hr = sD[px*SD_STRIDE + c      ] + __ldg(&h2h_b[c      ]);
            float hu = sD[px*SD_STRIDE + c +  64] + __ldg(&h2h_b[c +  64]);
            float hm = sD[px*SD_STRIDE + c + 128] + __ldg(&h2h_b[c + 128]);
            float ir = i2hb[(size_t)(c      )*HW + p];
            float iu = i2hb[(size_t)(c +  64)*HW + p];
            float im = i2hb[(size_t)(c + 128)*HW + p];
            float hpv = hp[((size_t)b*HID + c)*HW + p];
            float rg = 1.f / (1.f + expf(-(ir + hr)));
            float ug = 1.f / (1.f + expf(-(iu + hu)));
            float nm = tanhf(im + rg * hm);
            out[((size_t)b*HID + c)*HW + p] = ug * hpv + (1.f - ug) * nm;
        }
    }
}

// ---------------- launch ---------------------------------------------------
extern "C" void kernel_launch(void* const* d_in, const int* in_sizes, int n_in,
                              void* d_out, int out_size)
{
    const float* x       = (const float*)d_in[0];
    const float* h_prev  = (const float*)d_in[1];
    const float* i2h_w   = (const float*)d_in[2];
    const float* i2h_b   = (const float*)d_in[3];
    const float* h2h_w   = (const float*)d_in[4];
    const float* h2h_b   = (const float*)d_in[5];
    const float* i2f_w   = (const float*)d_in[6];
    const float* i2f_b   = (const float*)d_in[7];
    const float* h2f_w   = (const float*)d_in[8];
    const float* h2f_b   = (const float*)d_in[9];
    const float* flows_w = (const float*)d_in[10];
    const float* flows_b = (const float*)d_in[11];
    float* out = (float*)d_out;

    cudaFuncSetAttribute(k_main_mma, cudaFuncAttributeMaxDynamicSharedMemorySize,
                         SMEM_MMA_BYTES);

    dim3 gt(HW/32, HID/32, BATCH);
    k_transpose<<<gt, dim3(32, 8)>>>(h_prev);

    dim3 gf(2, 30, BATCH);
    k_f<<<gf, 240>>>(x, h_prev, i2f_w, i2f_b, h2f_w, h2f_b);
    k_i2h<<<gf, 240>>>(x, i2h_w, i2h_b);

    dim3 gfl(30, BATCH);
    k_flows<<<gfl, 240>>>(flows_w, flows_b);

    dim3 gm((HW + 127)/128, BATCH);
    k_main_mma<<<gm, 256, SMEM_MMA_BYTES>>>(h_prev, h2h_w, h2h_b, out);
}

// round 6
// speedup vs baseline: 2.2036x; 1.1527x over previous
#include <cuda_runtime.h>
#include <math.h>
#include <stdint.h>

#define BATCH 8
#define NCIN 8
#define HID 64
#define LNK 9
#define HH 120
#define WW 120
#define HW (HH*WW)      // 14400
#define C3 (3*HID)      // 192

typedef unsigned long long ull;

__device__ __forceinline__ ull pack2(float a, float b) {
    ull r; asm("mov.b64 %0, {%1,%2};" : "=l"(r) : "f"(a), "f"(b)); return r;
}
__device__ __forceinline__ ull bcast2(float a) { return pack2(a, a); }
__device__ __forceinline__ void fma2(ull& d, ull a, ull b) {
    asm("fma.rn.f32x2 %0, %1, %2, %0;" : "+l"(d) : "l"(a), "l"(b));
}
__device__ __forceinline__ float2 unpack2(ull v) {
    float2 r; asm("mov.b64 {%0,%1}, %2;" : "=f"(r.x), "=f"(r.y) : "l"(v)); return r;
}
__device__ __forceinline__ uint32_t f2tf32(float v) {
    uint32_t r; asm("cvt.rna.tf32.f32 %0, %1;" : "=r"(r) : "f"(v)); return r;
}
__device__ __forceinline__ void mma_tf32(float* d,
    uint32_t a0, uint32_t a1, uint32_t a2, uint32_t a3,
    uint32_t b0, uint32_t b1)
{
    asm volatile("mma.sync.aligned.m16n8k8.row.col.f32.tf32.tf32.f32 "
        "{%0,%1,%2,%3}, {%4,%5,%6,%7}, {%8,%9}, {%0,%1,%2,%3};"
        : "+f"(d[0]), "+f"(d[1]), "+f"(d[2]), "+f"(d[3])
        : "r"(a0), "r"(a1), "r"(a2), "r"(a3), "r"(b0), "r"(b1));
}

// -------- scratch (device globals) ----------------------------------------
__device__ float    g_f[BATCH*32*HW];
__device__ float    g_flows[BATCH*2*LNK*HW];
__device__ float    g_i2h[(size_t)BATCH*C3*HW];
__device__ float4   g_hT4[(size_t)BATCH*HW*16];    // h_prev [b][p][64]
__device__ float    g_xhT[(size_t)BATCH*HW*72];    // [b][p][72]: x(8) + h(64)
__device__ uint32_t g_wf[25*32*72];                // conv-f weights, tf32, k-permuted

// ---------------- transpose h_prev NCHW -> NHWC (+ xh channels 8..71) -----
__global__ void k_transpose(const float* __restrict__ hp)
{
    __shared__ float t[32][33];
    int b  = blockIdx.z;
    int c0 = blockIdx.y * 32;
    int p0 = blockIdx.x * 32;
    int tx = threadIdx.x, ty = threadIdx.y;
    float* hT = (float*)g_hT4;
#pragma unroll
    for (int k = 0; k < 4; k++) {
        int c = c0 + ty + k*8;
        t[ty + k*8][tx] = hp[((size_t)b*HID + c)*HW + p0 + tx];
    }
    __syncthreads();
#pragma unroll
    for (int k = 0; k < 4; k++) {
        int p = p0 + ty + k*8;
        float v = t[tx][ty + k*8];
        hT[((size_t)b*HW + p)*HID + c0 + tx] = v;
        g_xhT[((size_t)b*HW + p)*72 + 8 + c0 + tx] = v;
    }
}

// x channels into g_xhT cols 0..7
__global__ void k_xpose(const float* __restrict__ x)
{
    int b  = blockIdx.z;
    int p0 = blockIdx.x * 32;
    int tx = threadIdx.x, ty = threadIdx.y;   // (32, 8)
    float v = x[((size_t)b*NCIN + ty)*HW + p0 + tx];
    g_xhT[((size_t)b*HW + p0 + tx)*72 + ty] = v;
}

// conv-f weights -> g_wf[tap][oc][72] tf32, k-permuted within k8 blocks
__global__ void k_prep_w(const float* __restrict__ i2f_w,
                         const float* __restrict__ h2f_w)
{
    int idx = blockIdx.x*256 + threadIdx.x;
    if (idx >= 25*32*72) return;
    int t  = idx / (32*72);
    int r  = idx % (32*72);
    int oc = r / 72, k = r % 72;
    float v = (k < 8) ? i2f_w[((size_t)oc*NCIN + k)*25 + t]
                      : h2f_w[((size_t)oc*HID + (k-8))*25 + t];
    int phys = (k >> 3)*8 + ((k >> 2) & 1) + 2*(k & 3);
    g_wf[t*(32*72) + oc*72 + phys] = f2tf32(v);
}

// ==========================================================================
// k_f_mma: f = relu(conv5x5(xh; wf)) via mma.sync tf32
// CTA = 1 output row (M=120->128 px) x 32 oc, 256 thr (8 warps).
// Loop dy: stage input row [132 cols][72 ch]; dx taps reuse it with row shift.
// ==========================================================================
#define KF_AS 76
#define KF_AROWS 132
#define KF_OFF_B (KF_AROWS*KF_AS*4)               // 40128
#define KF_SMEM  (KF_OFF_B + 160*KF_AS*4)         // 88768

__global__ __launch_bounds__(256, 2) void k_f_mma(
    const float* __restrict__ i2f_b, const float* __restrict__ h2f_b)
{
    extern __shared__ char sm[];
    uint32_t* sA = (uint32_t*)sm;
    uint32_t* sB = (uint32_t*)(sm + KF_OFF_B);

    int b   = blockIdx.y;
    int y0  = blockIdx.x;
    int tid = threadIdx.x;
    int wid = tid >> 5, lane = tid & 31;
    int warpM = wid & 3, warpN = wid >> 2;
    int lq = lane >> 2, lr = lane & 3;

    float acc[2][2][4];
#pragma unroll
    for (int mi = 0; mi < 2; mi++)
#pragma unroll
        for (int ni = 0; ni < 2; ni++)
#pragma unroll
            for (int j = 0; j < 4; j++) acc[mi][ni][j] = 0.f;

    // zero pad rows 124..131 (read by dx-shift for discarded outputs)
    for (int i = tid; i < 8*KF_AS; i += 256)
        sA[124*KF_AS + i] = 0;

    const float* xh = g_xhT + (size_t)b*HW*72;

    for (int dy = 0; dy < 5; dy++) {
        __syncthreads();
        int iy = y0 + dy - 2;
        // stage A: input row iy, cols -2..121 -> rows 0..123, tf32 k-permuted
        for (int idx = tid; idx < 124*18; idx += 256) {
            int col = idx / 18, kq = idx % 18;
            int gx = col - 2;
            float4 v = make_float4(0.f, 0.f, 0.f, 0.f);
            if (iy >= 0 && iy < HH && gx >= 0 && gx < WW)
                v = *(const float4*)&xh[((size_t)iy*WW + gx)*72 + kq*4];
            int base = col*KF_AS + (kq >> 1)*8 + (kq & 1);
            sA[base    ] = f2tf32(v.x);
            sA[base + 2] = f2tf32(v.y);
            sA[base + 4] = f2tf32(v.z);
            sA[base + 6] = f2tf32(v.w);
        }
        // stage B: taps dy*5..dy*5+4 (already permuted tf32 in g_wf)
        const uint4* wsrc = (const uint4*)&g_wf[dy*5*(32*72)];
        for (int idx = tid; idx < 5*32*18; idx += 256) {
            int row = idx / 18, kq = idx % 18;     // row = dx*32 + oc
            uint4 v = wsrc[row*18 + kq];
            uint32_t* d = &sB[row*KF_AS + kq*4];
            d[0] = v.x; d[1] = v.y; d[2] = v.z; d[3] = v.w;
        }
        __syncthreads();

#pragma unroll
        for (int dx = 0; dx < 5; dx++) {
            const uint32_t* Ab = sA + (warpM*32 + dx + lq)*KF_AS;
            const uint32_t* Bb = sB + (dx*32 + warpN*16 + lq)*KF_AS;
#pragma unroll
            for (int kb = 0; kb < 9; kb++) {
                int col = kb*8 + 2*lr;
                uint2 a00 = *(const uint2*)&Ab[col];
                uint2 a01 = *(const uint2*)&Ab[ 8*KF_AS + col];
                uint2 a10 = *(const uint2*)&Ab[16*KF_AS + col];
                uint2 a11 = *(const uint2*)&Ab[24*KF_AS + col];
                uint2 b0  = *(const uint2*)&Bb[col];
                uint2 b1  = *(const uint2*)&Bb[ 8*KF_AS + col];
                mma_tf32(acc[0][0], a00.x, a01.x, a00.y, a01.y, b0.x, b0.y);
                mma_tf32(acc[0][1], a00.x, a01.x, a00.y, a01.y, b1.x, b1.y);
                mma_tf32(acc[1][0], a10.x, a11.x, a10.y, a11.y, b0.x, b0.y);
                mma_tf32(acc[1][1], a10.x, a11.x, a10.y, a11.y, b1.x, b1.y);
            }
        }
    }

    // epilogue: bias + relu -> g_f (NCHW)
#pragma unroll
    for (int ni = 0; ni < 2; ni++) {
        int ocA = warpN*16 + ni*8 + 2*lr, ocB = ocA + 1;
        float bA = __ldg(&i2f_b[ocA]) + __ldg(&h2f_b[ocA]);
        float bB = __ldg(&i2f_b[ocB]) + __ldg(&h2f_b[ocB]);
        float* fA = &g_f[((size_t)b*32 + ocA)*HW + (size_t)y0*WW];
        float* fB = &g_f[((size_t)b*32 + ocB)*HW + (size_t)y0*WW];
#pragma unroll
        for (int mi = 0; mi < 2; mi++) {
            int x0 = warpM*32 + mi*16 + lq;
            int x1 = x0 + 8;
            if (x0 < WW) {
                fA[x0] = fmaxf(acc[mi][ni][0] + bA, 0.f);
                fB[x0] = fmaxf(acc[mi][ni][1] + bB, 0.f);
            }
            if (x1 < WW) {
                fA[x1] = fmaxf(acc[mi][ni][2] + bA, 0.f);
                fB[x1] = fmaxf(acc[mi][ni][3] + bB, 0.f);
            }
        }
    }
}

// ==========================================================================
// flows = conv5x5(f; flows_w): 32 ch -> 18 -- f32x2, oc-packed
// ==========================================================================
__global__ __launch_bounds__(240, 2) void k_flows(
    const float* __restrict__ flows_w, const float* __restrict__ flows_b)
{
    __shared__ float sp[8][8*124];
    __shared__ float ws[8*25*20];

    int b   = blockIdx.y;
    int ty0 = blockIdx.x * 4;
    int tid = threadIdx.x;
    int ocg = tid / 120;
    int pt  = tid % 120;
    int r   = pt / 30;
    int cq  = (pt % 30) * 4;
    int o0  = ocg * 9;
    int o0s = ocg * 10;

    ull acc2[4][4];
    float acc8[4];
#pragma unroll
    for (int p = 0; p < 4; p++) {
        acc8[p] = 0.f;
#pragma unroll
        for (int j = 0; j < 4; j++) acc2[p][j] = 0ull;
    }

    for (int chunk = 0; chunk < 4; chunk++) {
        __syncthreads();
        const float* src = g_f + ((size_t)b*32 + chunk*8)*HW;
        for (int idx = tid; idx < 8*992; idx += 240) {
            int ch = idx / 992, rem = idx % 992;
            int row = rem / 124, col = rem % 124;
            int gy = ty0 - 2 + row, gx = col - 2;
            float v = 0.f;
            if (gy >= 0 && gy < HH && gx >= 0 && gx < WW)
                v = src[(size_t)ch*HW + gy*WW + gx];
            sp[ch][row*124 + col] = v;
        }
        for (int idx = tid; idx < 3600; idx += 240) {
            int oc = idx % 18, rest = idx / 18;
            int ic = rest / 25, t = rest % 25;
            int slot = oc + (oc >= 9 ? 1 : 0);
            ws[rest*20 + slot] = flows_w[(size_t)oc*(32*25) + (chunk*8 + ic)*25 + t];
        }
        __syncthreads();

#pragma unroll 2
        for (int ic = 0; ic < 8; ic++) {
            float pr[5][8];
#pragma unroll
            for (int dy = 0; dy < 5; dy++) {
                float4 a = *(const float4*)&sp[ic][(r+dy)*124 + cq];
                float4 bb = *(const float4*)&sp[ic][(r+dy)*124 + cq + 4];
                pr[dy][0]=a.x; pr[dy][1]=a.y; pr[dy][2]=a.z; pr[dy][3]=a.w;
                pr[dy][4]=bb.x; pr[dy][5]=bb.y; pr[dy][6]=bb.z; pr[dy][7]=bb.w;
            }
#pragma unroll
            for (int t = 0; t < 25; t++) {
                int dy = t / 5, dx = t % 5;
                const ull* wp = (const ull*)&ws[(ic*25 + t)*20 + o0s];
                ull w2[4] = {wp[0], wp[1], wp[2], wp[3]};
                float w8 = ws[(ic*25 + t)*20 + o0s + 8];
#pragma unroll
                for (int j = 0; j < 4; j++) {
                    float pv = pr[dy][dx + j];
                    ull pb = bcast2(pv);
                    fma2(acc2[0][j], w2[0], pb);
                    fma2(acc2[1][j], w2[1], pb);
                    fma2(acc2[2][j], w2[2], pb);
                    fma2(acc2[3][j], w2[3], pb);
                    acc8[j] += w8 * pv;
                }
            }
        }
    }

    size_t base = (ty0+r)*WW + cq;
#pragma unroll
    for (int p = 0; p < 4; p++) {
        float2 v0 = unpack2(acc2[p][0]);
        float2 v1 = unpack2(acc2[p][1]);
        float2 v2 = unpack2(acc2[p][2]);
        float2 v3 = unpack2(acc2[p][3]);
        int ocA = o0 + 2*p, ocB = ocA + 1;
        float bA = __ldg(&flows_b[ocA]);
        float bB = __ldg(&flows_b[ocB]);
        float4 oA, oB;
        oA.x = v0.x + bA; oA.y = v1.x + bA; oA.z = v2.x + bA; oA.w = v3.x + bA;
        oB.x = v0.y + bB; oB.y = v1.y + bB; oB.z = v2.y + bB; oB.w = v3.y + bB;
        *(float4*)&g_flows[((size_t)b*(2*LNK) + ocA)*HW + base] = oA;
        *(float4*)&g_flows[((size_t)b*(2*LNK) + ocB)*HW + base] = oB;
    }
    {
        int oc = o0 + 8;
        float bias = __ldg(&flows_b[oc]);
        float4 o;
        o.x = acc8[0] + bias; o.y = acc8[1] + bias;
        o.z = acc8[2] + bias; o.w = acc8[3] + bias;
        *(float4*)&g_flows[((size_t)b*(2*LNK) + oc)*HW + base] = o;
    }
}

// ==========================================================================
// i2h = conv3x3(x; i2h_w): 8 ch -> 192 -- f32x2, oc-packed
// ==========================================================================
__global__ __launch_bounds__(240, 2) void k_i2h(
    const float* __restrict__ x,
    const float* __restrict__ i2h_w, const float* __restrict__ i2h_b)
{
    __shared__ float sp[8][6*64];
    __shared__ float ws[72*64];

    int b   = blockIdx.z;
    int ty0 = blockIdx.y * 4;
    int c0  = blockIdx.x * 60;
    int tid = threadIdx.x;
    int ocg = tid / 60;
    int pt  = tid % 60;
    int r   = pt / 15;
    int cq  = (pt % 15) * 4;
    int o0g = ocg * 16;

    for (int idx = tid; idx < 8*384; idx += 240) {
        int ch = idx / 384, rem = idx % 384;
        int row = rem >> 6, col = rem & 63;
        int gy = ty0 - 1 + row, gx = c0 - 1 + col;
        float v = 0.f;
        if (gy >= 0 && gy < HH && gx >= 0 && gx < WW)
            v = x[((size_t)b*NCIN + ch)*HW + gy*WW + gx];
        sp[ch][row*64 + col] = v;
    }

    for (int p = 0; p < 3; p++) {
        int ocbase = p * 64;
        __syncthreads();
        for (int idx = tid; idx < 72*64; idx += 240) {
            int oc = idx & 63, rest = idx >> 6;
            ws[rest*64 + oc] = i2h_w[(size_t)(ocbase + oc)*72 + rest];
        }
        __syncthreads();

        ull acc2[8][4];
#pragma unroll
        for (int k = 0; k < 8; k++)
#pragma unroll
            for (int j = 0; j < 4; j++) acc2[k][j] = 0ull;

#pragma unroll 2
        for (int ic = 0; ic < 8; ic++) {
            float pr[3][8];
#pragma unroll
            for (int dy = 0; dy < 3; dy++) {
                float4 a = *(const float4*)&sp[ic][(r+dy)*64 + cq];
                float4 bb = *(const float4*)&sp[ic][(r+dy)*64 + cq + 4];
                pr[dy][0]=a.x; pr[dy][1]=a.y; pr[dy][2]=a.z; pr[dy][3]=a.w;
                pr[dy][4]=bb.x; pr[dy][5]=bb.y; pr[dy][6]=bb.z; pr[dy][7]=bb.w;
            }
#pragma unroll
            for (int t = 0; t < 9; t++) {
                int dy = t / 3, dx = t % 3;
                const ulonglong2* wp = (const ulonglong2*)&ws[(ic*9 + t)*64 + o0g];
                ulonglong2 wA = wp[0], wB = wp[1], wC = wp[2], wD = wp[3];
                ull w2[8] = {wA.x, wA.y, wB.x, wB.y, wC.x, wC.y, wD.x, wD.y};
#pragma unroll
                for (int j = 0; j < 4; j++) {
                    ull pb = bcast2(pr[dy][dx + j]);
#pragma unroll
                    for (int k = 0; k < 8; k++)
                        fma2(acc2[k][j], w2[k], pb);
                }
            }
        }

        size_t base = (ty0+r)*WW + c0 + cq;
#pragma unroll
        for (int k = 0; k < 8; k++) {
            float2 v0 = unpack2(acc2[k][0]);
            float2 v1 = unpack2(acc2[k][1]);
            float2 v2 = unpack2(acc2[k][2]);
            float2 v3 = unpack2(acc2[k][3]);
            int ocA = ocbase + o0g + 2*k, ocB = ocA + 1;
            float bA = __ldg(&i2h_b[ocA]);
            float bB = __ldg(&i2h_b[ocB]);
            float4 oA, oB;
            oA.x = v0.x + bA; oA.y = v1.x + bA; oA.z = v2.x + bA; oA.w = v3.x + bA;
            oB.x = v0.y + bB; oB.y = v1.y + bB; oB.z = v2.y + bB; oB.w = v3.y + bB;
            *(float4*)&g_i2h[((size_t)b*C3 + ocA)*HW + base] = oA;
            *(float4*)&g_i2h[((size_t)b*C3 + ocB)*HW + base] = oB;
        }
        __syncthreads();
    }
}

// ==========================================================================
// k_main: fused warp(x9) + 1x1 conv via mma.sync tf32 + GRU gates
// ==========================================================================
#define SA_STRIDE 72
#define SB_STRIDE 72
#define OFF_GEO 0
#define OFF_A   4096
#define OFF_B   (OFF_A + 128*SA_STRIDE*4)          // 40960
#define PHASE1_BYTES (OFF_B + 192*SB_STRIDE*4)     // 96256
#define SD_STRIDE 194
#define SD_BYTES (128*SD_STRIDE*4)                 // 99328
#define SMEM_MMA_BYTES (SD_BYTES > PHASE1_BYTES ? SD_BYTES : PHASE1_BYTES)

__global__ __launch_bounds__(256, 1) void k_main_mma(
    const float* __restrict__ hp,
    const float* __restrict__ h2h_w, const float* __restrict__ h2h_b,
    float* __restrict__ out)
{
    extern __shared__ char sm[];
    float*    sgeo = (float*)(sm + OFF_GEO);          // [128][8]
    uint32_t* sA   = (uint32_t*)(sm + OFF_A);
    uint32_t* sB   = (uint32_t*)(sm + OFF_B);
    float*    sD   = (float*)sm;                      // phase 2 overlay

    int b   = blockIdx.y;
    int p0  = blockIdx.x * 128;
    int tid = threadIdx.x;
    int wid = tid >> 5, lane = tid & 31;
    int warpM = wid & 3, warpN = wid >> 2;
    int lq = lane >> 2, lr = lane & 3;

    float acc[2][12][4];
#pragma unroll
    for (int mi = 0; mi < 2; mi++)
#pragma unroll
        for (int ni = 0; ni < 12; ni++)
#pragma unroll
            for (int j = 0; j < 4; j++) acc[mi][ni][j] = 0.f;

    const float4* hT4 = g_hT4 + (size_t)b*HW*16;

    for (int l = 0; l < LNK; l++) {
        if (tid < 128) {
            int p = p0 + tid; if (p > HW-1) p = HW-1;
            int yc = p / WW, xc = p - yc*WW;
            float sx = (float)xc + g_flows[((size_t)b*(2*LNK) + 2*l    )*HW + p];
            float sy = (float)yc + g_flows[((size_t)b*(2*LNK) + 2*l + 1)*HW + p];
            float fx = floorf(sx), fy = floorf(sy);
            float wx1 = sx - fx, wy1 = sy - fy;
            float wx0 = 1.f - wx1, wy0 = 1.f - wy1;
            int ix0 = (int)fx, iy0 = (int)fy;
            bool vx0 = (ix0 >= 0) && (ix0 < WW);
            bool vx1 = (ix0 >= -1) && (ix0 < WW - 1);
            bool vy0 = (iy0 >= 0) && (iy0 < HH);
            bool vy1 = (iy0 >= -1) && (iy0 < HH - 1);
            int r0 = iy0*WW, r1 = r0 + WW;
            float* g = &sgeo[tid*8];
            g[0] = wy0*wx0; g[1] = wy0*wx1; g[2] = wy1*wx0; g[3] = wy1*wx1;
            ((int*)g)[4] = (vy0 && vx0) ? (r0 + ix0)     : -1;
            ((int*)g)[5] = (vy0 && vx1) ? (r0 + ix0 + 1) : -1;
            ((int*)g)[6] = (vy1 && vx0) ? (r1 + ix0)     : -1;
            ((int*)g)[7] = (vy1 && vx1) ? (r1 + ix0 + 1) : -1;
        }
        __syncthreads();

#pragma unroll
        for (int i = 0; i < 12; i++) {
            int q = i*256 + tid;
            int o = q >> 4, kq = q & 15;
            float4 w = *(const float4*)&h2h_w[(size_t)o*576 + l*64 + kq*4];
            int blk = kq >> 1;
            int base = o*SB_STRIDE + blk*8 + (kq & 1);
            sB[base    ] = f2tf32(w.x);
            sB[base + 2] = f2tf32(w.y);
            sB[base + 4] = f2tf32(w.z);
            sB[base + 6] = f2tf32(w.w);
        }

#pragma unroll
        for (int i = 0; i < 8; i++) {
            int item = i*256 + tid;
            int px = item >> 4, cg = item & 15;
            const float* g = &sgeo[px*8];
            float w00 = g[0], w01 = g[1], w10 = g[2], w11 = g[3];
            int i00 = ((const int*)g)[4], i01 = ((const int*)g)[5];
            int i10 = ((const int*)g)[6], i11 = ((const int*)g)[7];
            float ax=0.f, ay=0.f, az=0.f, aw=0.f;
            if (i00 >= 0) { float4 v = hT4[(size_t)i00*16 + cg];
                ax += w00*v.x; ay += w00*v.y; az += w00*v.z; aw += w00*v.w; }
            if (i01 >= 0) { float4 v = hT4[(size_t)i01*16 + cg];
                ax += w01*v.x; ay += w01*v.y; az += w01*v.z; aw += w01*v.w; }
            if (i10 >= 0) { float4 v = hT4[(size_t)i10*16 + cg];
                ax += w10*v.x; ay += w10*v.y; az += w10*v.z; aw += w10*v.w; }
            if (i11 >= 0) { float4 v = hT4[(size_t)i11*16 + cg];
                ax += w11*v.x; ay += w11*v.y; az += w11*v.z; aw += w11*v.w; }
            int blk = cg >> 1;
            int base = px*SA_STRIDE + blk*8 + (cg & 1);
            sA[base    ] = f2tf32(ax);
            sA[base + 2] = f2tf32(ay);
            sA[base + 4] = f2tf32(az);
            sA[base + 6] = f2tf32(aw);
        }
        __syncthreads();

        const uint32_t* Ab = sA + (warpM*32 + lq)*SA_STRIDE;
        const uint32_t* Bb = sB + (warpN*96 + lq)*SB_STRIDE;
#pragma unroll
        for (int kb = 0; kb < 8; kb++) {
            int col = kb*8 + 2*lr;
            uint2 a00 = *(const uint2*)&Ab[col];
            uint2 a01 = *(const uint2*)&Ab[8*SA_STRIDE + col];
            uint2 a10 = *(const uint2*)&Ab[16*SA_STRIDE + col];
            uint2 a11 = *(const uint2*)&Ab[24*SA_STRIDE + col];
#pragma unroll
            for (int ni = 0; ni < 12; ni++) {
                uint2 bb = *(const uint2*)&Bb[ni*8*SB_STRIDE + col];
                mma_tf32(acc[0][ni], a00.x, a01.x, a00.y, a01.y, bb.x, bb.y);
                mma_tf32(acc[1][ni], a10.x, a11.x, a10.y, a11.y, bb.x, bb.y);
            }
        }
        __syncthreads();
    }

#pragma unroll
    for (int mi = 0; mi < 2; mi++) {
        int rbase = warpM*32 + mi*16 + lq;
#pragma unroll
        for (int ni = 0; ni < 12; ni++) {
            int cc = warpN*96 + ni*8 + 2*lr;
            *(float2*)&sD[(rbase    )*SD_STRIDE + cc] = make_float2(acc[mi][ni][0], acc[mi][ni][1]);
            *(float2*)&sD[(rbase + 8)*SD_STRIDE + cc] = make_float2(acc[mi][ni][2], acc[mi][ni][3]);
        }
    }
    __syncthreads();

    const float* i2hb = g_i2h + (size_t)b*C3*HW;
#pragma unroll
    for (int it = 0; it < 32; it++) {
        int idx = it*256 + tid;
        int c = idx >> 7, px = idx & 127;
        int p = p0 + px;
        if (p < HW) {
            float hr = sD[px*SD_STRIDE + c      ] + __ldg(&h2h_b[c      ]);
            float hu = sD[px*SD_STRIDE + c +  64] + __ldg(&h2h_b[c +  64]);
            float hm = sD[px*SD_STRIDE + c + 128] + __ldg(&h2h_b[c + 128]);
            float ir = i2hb[(size_t)(c      )*HW + p];
            float iu = i2hb[(size_t)(c +  64)*HW + p];
            float im = i2hb[(size_t)(c + 128)*HW + p];
            float hpv = hp[((size_t)b*HID + c)*HW + p];
            float rg = 1.f / (1.f + expf(-(ir + hr)));
            float ug = 1.f / (1.f + expf(-(iu + hu)));
            float nm = tanhf(im + rg * hm);
            out[((size_t)b*HID + c)*HW + p] = ug * hpv + (1.f - ug) * nm;
        }
    }
}

// ---------------- launch ---------------------------------------------------
extern "C" void kernel_launch(void* const* d_in, const int* in_sizes, int n_in,
                              void* d_out, int out_size)
{
    const float* x       = (const float*)d_in[0];
    const float* h_prev  = (const float*)d_in[1];
    const float* i2h_w   = (const float*)d_in[2];
    const float* i2h_b   = (const float*)d_in[3];
    const float* h2h_w   = (const float*)d_in[4];
    const float* h2h_b   = (const float*)d_in[5];
    const float* i2f_w   = (const float*)d_in[6];
    const float* i2f_b   = (const float*)d_in[7];
    const float* h2f_w   = (const float*)d_in[8];
    const float* h2f_b   = (const float*)d_in[9];
    const float* flows_w = (const float*)d_in[10];
    const float* flows_b = (const float*)d_in[11];
    float* out = (float*)d_out;

    cudaFuncSetAttribute(k_main_mma, cudaFuncAttributeMaxDynamicSharedMemorySize,
                         SMEM_MMA_BYTES);
    cudaFuncSetAttribute(k_f_mma, cudaFuncAttributeMaxDynamicSharedMemorySize,
                         KF_SMEM);

    dim3 gt(HW/32, HID/32, BATCH);
    k_transpose<<<gt, dim3(32, 8)>>>(h_prev);

    dim3 gx(HW/32, 1, BATCH);
    k_xpose<<<gx, dim3(32, 8)>>>(x);

    k_prep_w<<<(25*32*72 + 255)/256, 256>>>(i2f_w, h2f_w);

    dim3 gfm(HH, BATCH);
    k_f_mma<<<gfm, 256, KF_SMEM>>>(i2f_b, h2f_b);

    dim3 gf(2, 30, BATCH);
    k_i2h<<<gf, 240>>>(x, i2h_w, i2h_b);

    dim3 gfl(30, BATCH);
    k_flows<<<gfl, 240>>>(flows_w, flows_b);

    dim3 gm((HW + 127)/128, BATCH);
    k_main_mma<<<gm, 256, SMEM_MMA_BYTES>>>(h_prev, h2h_w, h2h_b, out);
}

// round 7
// speedup vs baseline: 2.3242x; 1.0547x over previous
#include <cuda_runtime.h>
#include <math.h>
#include <stdint.h>

#define BATCH 8
#define NCIN 8
#define HID 64
#define LNK 9
#define HH 120
#define WW 120
#define HW (HH*WW)      // 14400
#define C3 (3*HID)      // 192

typedef unsigned long long ull;

__device__ __forceinline__ ull pack2(float a, float b) {
    ull r; asm("mov.b64 %0, {%1,%2};" : "=l"(r) : "f"(a), "f"(b)); return r;
}
__device__ __forceinline__ ull bcast2(float a) { return pack2(a, a); }
__device__ __forceinline__ void fma2(ull& d, ull a, ull b) {
    asm("fma.rn.f32x2 %0, %1, %2, %0;" : "+l"(d) : "l"(a), "l"(b));
}
__device__ __forceinline__ float2 unpack2(ull v) {
    float2 r; asm("mov.b64 {%0,%1}, %2;" : "=f"(r.x), "=f"(r.y) : "l"(v)); return r;
}
__device__ __forceinline__ uint32_t f2tf32(float v) {
    uint32_t r; asm("cvt.rna.tf32.f32 %0, %1;" : "=r"(r) : "f"(v)); return r;
}
__device__ __forceinline__ void mma_tf32(float* d,
    uint32_t a0, uint32_t a1, uint32_t a2, uint32_t a3,
    uint32_t b0, uint32_t b1)
{
    asm volatile("mma.sync.aligned.m16n8k8.row.col.f32.tf32.tf32.f32 "
        "{%0,%1,%2,%3}, {%4,%5,%6,%7}, {%8,%9}, {%0,%1,%2,%3};"
        : "+f"(d[0]), "+f"(d[1]), "+f"(d[2]), "+f"(d[3])
        : "r"(a0), "r"(a1), "r"(a2), "r"(a3), "r"(b0), "r"(b1));
}

// permutation: within each 8-k block, phys slot of logical k:
//   q = ((k>>2)&1) + 2*(k&3);  inverse: k = (q&1)*4 + (q>>1)

// -------- scratch (device globals) ----------------------------------------
__device__ float    g_f[BATCH*32*HW];
__device__ float    g_flows[BATCH*2*LNK*HW];
__device__ float    g_i2h[(size_t)BATCH*C3*HW];
__device__ float4   g_hT4[(size_t)BATCH*HW*16];    // h_prev [b][p][64], fp32, slot-permuted
__device__ uint32_t g_xhT[(size_t)BATCH*HW*72];    // [b][p][72] tf32 bits, permuted: x(8)+h(64)
__device__ uint32_t g_wf[25*32*72];                // conv-f weights, tf32, permuted
__device__ uint32_t g_wB[LNK*192*64];              // h2h weights per link, tf32, permuted
__device__ uint32_t g_wI[192*72];                  // i2h weights, tf32, permuted (blocks=taps)

// ---------------- transpose h_prev NCHW -> permuted NHWC -------------------
__global__ void k_transpose(const float* __restrict__ hp)
{
    __shared__ float t[32][33];
    int b  = blockIdx.z;
    int c0 = blockIdx.y * 32;
    int p0 = blockIdx.x * 32;
    int tx = threadIdx.x, ty = threadIdx.y;
    float* hT = (float*)g_hT4;
#pragma unroll
    for (int k = 0; k < 4; k++) {
        int c = c0 + ty + k*8;
        t[ty + k*8][tx] = hp[((size_t)b*HID + c)*HW + p0 + tx];
    }
    __syncthreads();
    int c = c0 + tx;
    int slot = (c >> 3)*8 + ((c >> 2) & 1) + 2*(c & 3);
#pragma unroll
    for (int k = 0; k < 4; k++) {
        int p = p0 + ty + k*8;
        float v = t[tx][ty + k*8];
        hT[((size_t)b*HW + p)*HID + slot] = v;
        g_xhT[((size_t)b*HW + p)*72 + 8 + slot] = f2tf32(v);
    }
}

// x channels -> g_xhT block 0 (permuted, tf32)
__global__ void k_xpose(const float* __restrict__ x)
{
    int b  = blockIdx.z;
    int p0 = blockIdx.x * 32;
    int tx = threadIdx.x, ty = threadIdx.y;   // (32, 8)
    float v = x[((size_t)b*NCIN + ty)*HW + p0 + tx];
    int slot = ((ty >> 2) & 1) + 2*(ty & 3);
    g_xhT[((size_t)b*HW + p0 + tx)*72 + slot] = f2tf32(v);
}

// conv-f weights -> g_wf[tap][oc][72] tf32 permuted
__global__ void k_prep_w(const float* __restrict__ i2f_w,
                         const float* __restrict__ h2f_w)
{
    int idx = blockIdx.x*256 + threadIdx.x;
    if (idx >= 25*32*72) return;
    int t  = idx / (32*72);
    int r  = idx % (32*72);
    int oc = r / 72, k = r % 72;
    float v = (k < 8) ? i2f_w[((size_t)oc*NCIN + k)*25 + t]
                      : h2f_w[((size_t)oc*HID + (k-8))*25 + t];
    int phys = (k >> 3)*8 + ((k >> 2) & 1) + 2*(k & 3);
    g_wf[t*(32*72) + oc*72 + phys] = f2tf32(v);
}

// h2h weights -> g_wB[l][o][64] tf32 permuted
__global__ void k_prep_wB(const float* __restrict__ h2h_w)
{
    int idx = blockIdx.x*256 + threadIdx.x;
    if (idx >= LNK*192*64) return;
    int l = idx / (192*64);
    int r = idx % (192*64);
    int o = r / 64, p = r % 64;
    int k = (p & ~7) + ((p & 1) << 2) + ((p & 7) >> 1);
    g_wB[idx] = f2tf32(h2h_w[(size_t)o*576 + l*64 + k]);
}

// i2h weights -> g_wI[o][72] tf32 permuted; k-block = tap t, within = x-ch
__global__ void k_prep_wI(const float* __restrict__ i2h_w)
{
    int idx = blockIdx.x*256 + threadIdx.x;
    if (idx >= 192*72) return;
    int o = idx / 72, p = idx % 72;
    int t = p >> 3, q = p & 7;
    int c = ((q & 1) << 2) + (q >> 1);
    g_wI[idx] = f2tf32(i2h_w[(size_t)o*72 + c*9 + t]);
}

// ==========================================================================
// k_f_mma: f = relu(conv5x5(xh; wf)) via mma.sync tf32
// CTA = 1 output row x 32 oc, 256 thr. A staging = plain uint4 copies.
// ==========================================================================
#define KF_AS 76
#define KF_AROWS 132
#define KF_OFF_B (KF_AROWS*KF_AS*4)               // 40128
#define KF_SMEM  (KF_OFF_B + 160*KF_AS*4)         // 88768

__global__ __launch_bounds__(256, 2) void k_f_mma(
    const float* __restrict__ i2f_b, const float* __restrict__ h2f_b)
{
    extern __shared__ char sm[];
    uint32_t* sA = (uint32_t*)sm;
    uint32_t* sB = (uint32_t*)(sm + KF_OFF_B);

    int b   = blockIdx.y;
    int y0  = blockIdx.x;
    int tid = threadIdx.x;
    int wid = tid >> 5, lane = tid & 31;
    int warpM = wid & 3, warpN = wid >> 2;
    int lq = lane >> 2, lr = lane & 3;

    float acc[2][2][4];
#pragma unroll
    for (int mi = 0; mi < 2; mi++)
#pragma unroll
        for (int ni = 0; ni < 2; ni++)
#pragma unroll
            for (int j = 0; j < 4; j++) acc[mi][ni][j] = 0.f;

    for (int i = tid; i < 8*KF_AS; i += 256)
        sA[124*KF_AS + i] = 0;

    const uint4* xh4 = (const uint4*)(g_xhT + (size_t)b*HW*72);

    for (int dy = 0; dy < 5; dy++) {
        __syncthreads();
        int iy = y0 + dy - 2;
        // stage A: input row iy, cols -2..121 -> rows 0..123 (uint4 copies)
        for (int idx = tid; idx < 124*18; idx += 256) {
            int col = idx / 18, kq = idx % 18;
            int gx = col - 2;
            uint4 v = make_uint4(0u, 0u, 0u, 0u);
            if (iy >= 0 && iy < HH && gx >= 0 && gx < WW)
                v = xh4[((size_t)iy*WW + gx)*18 + kq];
            *(uint4*)&sA[col*KF_AS + kq*4] = v;
        }
        // stage B: taps dy*5..dy*5+4 (already permuted tf32)
        const uint4* wsrc = (const uint4*)&g_wf[dy*5*(32*72)];
        for (int idx = tid; idx < 5*32*18; idx += 256) {
            int row = idx / 18, kq = idx % 18;
            *(uint4*)&sB[row*KF_AS + kq*4] = wsrc[row*18 + kq];
        }
        __syncthreads();

#pragma unroll
        for (int dx = 0; dx < 5; dx++) {
            const uint32_t* Ab = sA + (warpM*32 + dx + lq)*KF_AS;
            const uint32_t* Bb = sB + (dx*32 + warpN*16 + lq)*KF_AS;
#pragma unroll
            for (int kb = 0; kb < 9; kb++) {
                int col = kb*8 + 2*lr;
                uint2 a00 = *(const uint2*)&Ab[col];
                uint2 a01 = *(const uint2*)&Ab[ 8*KF_AS + col];
                uint2 a10 = *(const uint2*)&Ab[16*KF_AS + col];
                uint2 a11 = *(const uint2*)&Ab[24*KF_AS + col];
                uint2 b0  = *(const uint2*)&Bb[col];
                uint2 b1  = *(const uint2*)&Bb[ 8*KF_AS + col];
                mma_tf32(acc[0][0], a00.x, a01.x, a00.y, a01.y, b0.x, b0.y);
                mma_tf32(acc[0][1], a00.x, a01.x, a00.y, a01.y, b1.x, b1.y);
                mma_tf32(acc[1][0], a10.x, a11.x, a10.y, a11.y, b0.x, b0.y);
                mma_tf32(acc[1][1], a10.x, a11.x, a10.y, a11.y, b1.x, b1.y);
            }
        }
    }

#pragma unroll
    for (int ni = 0; ni < 2; ni++) {
        int ocA = warpN*16 + ni*8 + 2*lr, ocB = ocA + 1;
        float bA = __ldg(&i2f_b[ocA]) + __ldg(&h2f_b[ocA]);
        float bB = __ldg(&i2f_b[ocB]) + __ldg(&h2f_b[ocB]);
        float* fA = &g_f[((size_t)b*32 + ocA)*HW + (size_t)y0*WW];
        float* fB = &g_f[((size_t)b*32 + ocB)*HW + (size_t)y0*WW];
#pragma unroll
        for (int mi = 0; mi < 2; mi++) {
            int x0 = warpM*32 + mi*16 + lq;
            int x1 = x0 + 8;
            if (x0 < WW) {
                fA[x0] = fmaxf(acc[mi][ni][0] + bA, 0.f);
                fB[x0] = fmaxf(acc[mi][ni][1] + bB, 0.f);
            }
            if (x1 < WW) {
                fA[x1] = fmaxf(acc[mi][ni][2] + bA, 0.f);
                fB[x1] = fmaxf(acc[mi][ni][3] + bB, 0.f);
            }
        }
    }
}

// ==========================================================================
// k_i2h_mma: i2h = conv3x3(x; i2h_w) via mma.sync tf32
// CTA = 1 output row x 192 oc, 256 thr. K = 72 = 9 taps x 8 x-channels.
// ==========================================================================
#define KI_AS 76
#define KI_OFF_B (128*KI_AS*4)                    // 38912
#define KI_SMEM  (KI_OFF_B + 192*KI_AS*4)         // 97280

__global__ __launch_bounds__(256, 1) void k_i2h_mma(const float* __restrict__ i2h_b)
{
    extern __shared__ char sm[];
    uint32_t* sA = (uint32_t*)sm;
    uint32_t* sB = (uint32_t*)(sm + KI_OFF_B);

    int b   = blockIdx.y;
    int y0  = blockIdx.x;
    int tid = threadIdx.x;
    int wid = tid >> 5, lane = tid & 31;
    int warpM = wid & 3, warpN = wid >> 2;
    int lq = lane >> 2, lr = lane & 3;

    const uint4* xh4 = (const uint4*)(g_xhT + (size_t)b*HW*72);

    // stage A: [128 px][9 taps x 8 ch]; item = px*18 + t*2 + half
    for (int idx = tid; idx < 128*18; idx += 256) {
        int px = idx / 18, r = idx % 18;
        int t = r >> 1, half = r & 1;
        int dy = t / 3, dx = t % 3;
        int iy = y0 + dy - 1, gx = px + dx - 1;
        uint4 v = make_uint4(0u, 0u, 0u, 0u);
        if (iy >= 0 && iy < HH && gx >= 0 && gx < WW)
            v = xh4[((size_t)iy*WW + gx)*18 + half];   // x chans: first 8 of 72
        *(uint4*)&sA[px*KI_AS + t*8 + half*4] = v;
    }
    // stage B: [192 oc][72]
    {
        const uint4* wI4 = (const uint4*)g_wI;
        for (int idx = tid; idx < 192*18; idx += 256) {
            int o = idx / 18, kq = idx % 18;
            *(uint4*)&sB[o*KI_AS + kq*4] = wI4[idx];
        }
    }
    __syncthreads();

    float acc[2][12][4];
#pragma unroll
    for (int mi = 0; mi < 2; mi++)
#pragma unroll
        for (int ni = 0; ni < 12; ni++)
#pragma unroll
            for (int j = 0; j < 4; j++) acc[mi][ni][j] = 0.f;

    const uint32_t* Ab = sA + (warpM*32 + lq)*KI_AS;
    const uint32_t* Bb = sB + (warpN*96 + lq)*KI_AS;
#pragma unroll
    for (int kb = 0; kb < 9; kb++) {
        int col = kb*8 + 2*lr;
        uint2 a00 = *(const uint2*)&Ab[col];
        uint2 a01 = *(const uint2*)&Ab[ 8*KI_AS + col];
        uint2 a10 = *(const uint2*)&Ab[16*KI_AS + col];
        uint2 a11 = *(const uint2*)&Ab[24*KI_AS + col];
#pragma unroll
        for (int ni = 0; ni < 12; ni++) {
            uint2 bb = *(const uint2*)&Bb[ni*8*KI_AS + col];
            mma_tf32(acc[0][ni], a00.x, a01.x, a00.y, a01.y, bb.x, bb.y);
            mma_tf32(acc[1][ni], a10.x, a11.x, a10.y, a11.y, bb.x, bb.y);
        }
    }

    // epilogue: bias -> g_i2h NCHW
#pragma unroll
    for (int ni = 0; ni < 12; ni++) {
        int ocA = warpN*96 + ni*8 + 2*lr, ocB = ocA + 1;
        float bA = __ldg(&i2h_b[ocA]);
        float bB = __ldg(&i2h_b[ocB]);
        float* oA = &g_i2h[((size_t)b*C3 + ocA)*HW + (size_t)y0*WW];
        float* oB = &g_i2h[((size_t)b*C3 + ocB)*HW + (size_t)y0*WW];
#pragma unroll
        for (int mi = 0; mi < 2; mi++) {
            int x0 = warpM*32 + mi*16 + lq;
            int x1 = x0 + 8;
            if (x0 < WW) {
                oA[x0] = acc[mi][ni][0] + bA;
                oB[x0] = acc[mi][ni][1] + bB;
            }
            if (x1 < WW) {
                oA[x1] = acc[mi][ni][2] + bA;
                oB[x1] = acc[mi][ni][3] + bB;
            }
        }
    }
}

// ==========================================================================
// flows = conv5x5(f; flows_w): 32 ch -> 18 -- f32x2, oc-packed
// ==========================================================================
__global__ __launch_bounds__(240, 2) void k_flows(
    const float* __restrict__ flows_w, const float* __restrict__ flows_b)
{
    __shared__ float sp[8][8*124];
    __shared__ float ws[8*25*20];

    int b   = blockIdx.y;
    int ty0 = blockIdx.x * 4;
    int tid = threadIdx.x;
    int ocg = tid / 120;
    int pt  = tid % 120;
    int r   = pt / 30;
    int cq  = (pt % 30) * 4;
    int o0  = ocg * 9;
    int o0s = ocg * 10;

    ull acc2[4][4];
    float acc8[4];
#pragma unroll
    for (int p = 0; p < 4; p++) {
        acc8[p] = 0.f;
#pragma unroll
        for (int j = 0; j < 4; j++) acc2[p][j] = 0ull;
    }

    for (int chunk = 0; chunk < 4; chunk++) {
        __syncthreads();
        const float* src = g_f + ((size_t)b*32 + chunk*8)*HW;
        for (int idx = tid; idx < 8*992; idx += 240) {
            int ch = idx / 992, rem = idx % 992;
            int row = rem / 124, col = rem % 124;
            int gy = ty0 - 2 + row, gx = col - 2;
            float v = 0.f;
            if (gy >= 0 && gy < HH && gx >= 0 && gx < WW)
                v = src[(size_t)ch*HW + gy*WW + gx];
            sp[ch][row*124 + col] = v;
        }
        for (int idx = tid; idx < 3600; idx += 240) {
            int oc = idx % 18, rest = idx / 18;
            int ic = rest / 25, t = rest % 25;
            int slot = oc + (oc >= 9 ? 1 : 0);
            ws[rest*20 + slot] = flows_w[(size_t)oc*(32*25) + (chunk*8 + ic)*25 + t];
        }
        __syncthreads();

#pragma unroll 2
        for (int ic = 0; ic < 8; ic++) {
            float pr[5][8];
#pragma unroll
            for (int dy = 0; dy < 5; dy++) {
                float4 a = *(const float4*)&sp[ic][(r+dy)*124 + cq];
                float4 bb = *(const float4*)&sp[ic][(r+dy)*124 + cq + 4];
                pr[dy][0]=a.x; pr[dy][1]=a.y; pr[dy][2]=a.z; pr[dy][3]=a.w;
                pr[dy][4]=bb.x; pr[dy][5]=bb.y; pr[dy][6]=bb.z; pr[dy][7]=bb.w;
            }
#pragma unroll
            for (int t = 0; t < 25; t++) {
                int dy = t / 5, dx = t % 5;
                const ull* wp = (const ull*)&ws[(ic*25 + t)*20 + o0s];
                ull w2[4] = {wp[0], wp[1], wp[2], wp[3]};
                float w8 = ws[(ic*25 + t)*20 + o0s + 8];
#pragma unroll
                for (int j = 0; j < 4; j++) {
                    float pv = pr[dy][dx + j];
                    ull pb = bcast2(pv);
                    fma2(acc2[0][j], w2[0], pb);
                    fma2(acc2[1][j], w2[1], pb);
                    fma2(acc2[2][j], w2[2], pb);
                    fma2(acc2[3][j], w2[3], pb);
                    acc8[j] += w8 * pv;
                }
            }
        }
    }

    size_t base = (ty0+r)*WW + cq;
#pragma unroll
    for (int p = 0; p < 4; p++) {
        float2 v0 = unpack2(acc2[p][0]);
        float2 v1 = unpack2(acc2[p][1]);
        float2 v2 = unpack2(acc2[p][2]);
        float2 v3 = unpack2(acc2[p][3]);
        int ocA = o0 + 2*p, ocB = ocA + 1;
        float bA = __ldg(&flows_b[ocA]);
        float bB = __ldg(&flows_b[ocB]);
        float4 oA, oB;
        oA.x = v0.x + bA; oA.y = v1.x + bA; oA.z = v2.x + bA; oA.w = v3.x + bA;
        oB.x = v0.y + bB; oB.y = v1.y + bB; oB.z = v2.y + bB; oB.w = v3.y + bB;
        *(float4*)&g_flows[((size_t)b*(2*LNK) + ocA)*HW + base] = oA;
        *(float4*)&g_flows[((size_t)b*(2*LNK) + ocB)*HW + base] = oB;
    }
    {
        int oc = o0 + 8;
        float bias = __ldg(&flows_b[oc]);
        float4 o;
        o.x = acc8[0] + bias; o.y = acc8[1] + bias;
        o.z = acc8[2] + bias; o.w = acc8[3] + bias;
        *(float4*)&g_flows[((size_t)b*(2*LNK) + oc)*HW + base] = o;
    }
}

// ==========================================================================
// k_main: fused warp(x9) + 1x1 conv via mma.sync tf32 + GRU gates
// ==========================================================================
#define SA_STRIDE 72
#define SB_STRIDE 72
#define OFF_GEO 0
#define OFF_A   4096
#define OFF_B   (OFF_A + 128*SA_STRIDE*4)          // 40960
#define PHASE1_BYTES (OFF_B + 192*SB_STRIDE*4)     // 96256
#define SD_STRIDE 194
#define SD_BYTES (128*SD_STRIDE*4)                 // 99328
#define SMEM_MMA_BYTES (SD_BYTES > PHASE1_BYTES ? SD_BYTES : PHASE1_BYTES)

__global__ __launch_bounds__(256, 1) void k_main_mma(
    const float* __restrict__ hp,
    const float* __restrict__ h2h_b,
    float* __restrict__ out)
{
    extern __shared__ char sm[];
    float*    sgeo = (float*)(sm + OFF_GEO);          // [128][8]
    uint32_t* sA   = (uint32_t*)(sm + OFF_A);
    uint32_t* sB   = (uint32_t*)(sm + OFF_B);
    float*    sD   = (float*)sm;                      // phase 2 overlay

    int b   = blockIdx.y;
    int p0  = blockIdx.x * 128;
    int tid = threadIdx.x;
    int wid = tid >> 5, lane = tid & 31;
    int warpM = wid & 3, warpN = wid >> 2;
    int lq = lane >> 2, lr = lane & 3;

    float acc[2][12][4];
#pragma unroll
    for (int mi = 0; mi < 2; mi++)
#pragma unroll
        for (int ni = 0; ni < 12; ni++)
#pragma unroll
            for (int j = 0; j < 4; j++) acc[mi][ni][j] = 0.f;

    const float4* hT4 = g_hT4 + (size_t)b*HW*16;

    for (int l = 0; l < LNK; l++) {
        if (tid < 128) {
            int p = p0 + tid; if (p > HW-1) p = HW-1;
            int yc = p / WW, xc = p - yc*WW;
            float sx = (float)xc + g_flows[((size_t)b*(2*LNK) + 2*l    )*HW + p];
            float sy = (float)yc + g_flows[((size_t)b*(2*LNK) + 2*l + 1)*HW + p];
            float fx = floorf(sx), fy = floorf(sy);
            float wx1 = sx - fx, wy1 = sy - fy;
            float wx0 = 1.f - wx1, wy0 = 1.f - wy1;
            int ix0 = (int)fx, iy0 = (int)fy;
            bool vx0 = (ix0 >= 0) && (ix0 < WW);
            bool vx1 = (ix0 >= -1) && (ix0 < WW - 1);
            bool vy0 = (iy0 >= 0) && (iy0 < HH);
            bool vy1 = (iy0 >= -1) && (iy0 < HH - 1);
            int r0 = iy0*WW, r1 = r0 + WW;
            float* g = &sgeo[tid*8];
            g[0] = wy0*wx0; g[1] = wy0*wx1; g[2] = wy1*wx0; g[3] = wy1*wx1;
            ((int*)g)[4] = (vy0 && vx0) ? (r0 + ix0)     : -1;
            ((int*)g)[5] = (vy0 && vx1) ? (r0 + ix0 + 1) : -1;
            ((int*)g)[6] = (vy1 && vx0) ? (r1 + ix0)     : -1;
            ((int*)g)[7] = (vy1 && vx1) ? (r1 + ix0 + 1) : -1;
        }
        __syncthreads();

        // stage B: uint4 copies from prestaged g_wB
        {
            const uint4* wB4 = (const uint4*)&g_wB[(size_t)l*192*64];
#pragma unroll
            for (int i = 0; i < 12; i++) {
                int q = i*256 + tid;               // 0..3071
                int o = q >> 4, kq = q & 15;
                *(uint4*)&sB[o*SB_STRIDE + kq*4] = wB4[o*16 + kq];
            }
        }

        // gather A: bilinear in fp32, contiguous STS.128
#pragma unroll
        for (int i = 0; i < 8; i++) {
            int item = i*256 + tid;
            int px = item >> 4, cg = item & 15;
            const float* g = &sgeo[px*8];
            float w00 = g[0], w01 = g[1], w10 = g[2], w11 = g[3];
            int i00 = ((const int*)g)[4], i01 = ((const int*)g)[5];
            int i10 = ((const int*)g)[6], i11 = ((const int*)g)[7];
            float ax=0.f, ay=0.f, az=0.f, aw=0.f;
            if (i00 >= 0) { float4 v = hT4[(size_t)i00*16 + cg];
                ax += w00*v.x; ay += w00*v.y; az += w00*v.z; aw += w00*v.w; }
            if (i01 >= 0) { float4 v = hT4[(size_t)i01*16 + cg];
                ax += w01*v.x; ay += w01*v.y; az += w01*v.z; aw += w01*v.w; }
            if (i10 >= 0) { float4 v = hT4[(size_t)i10*16 + cg];
                ax += w10*v.x; ay += w10*v.y; az += w10*v.z; aw += w10*v.w; }
            if (i11 >= 0) { float4 v = hT4[(size_t)i11*16 + cg];
                ax += w11*v.x; ay += w11*v.y; az += w11*v.z; aw += w11*v.w; }
            uint4 t;
            t.x = f2tf32(ax); t.y = f2tf32(ay); t.z = f2tf32(az); t.w = f2tf32(aw);
            *(uint4*)&sA[px*SA_STRIDE + cg*4] = t;
        }
        __syncthreads();

        const uint32_t* Ab = sA + (warpM*32 + lq)*SA_STRIDE;
        const uint32_t* Bb = sB + (warpN*96 + lq)*SB_STRIDE;
#pragma unroll
        for (int kb = 0; kb < 8; kb++) {
            int col = kb*8 + 2*lr;
            uint2 a00 = *(const uint2*)&Ab[col];
            uint2 a01 = *(const uint2*)&Ab[8*SA_STRIDE + col];
            uint2 a10 = *(const uint2*)&Ab[16*SA_STRIDE + col];
            uint2 a11 = *(const uint2*)&Ab[24*SA_STRIDE + col];
#pragma unroll
            for (int ni = 0; ni < 12; ni++) {
                uint2 bb = *(const uint2*)&Bb[ni*8*SB_STRIDE + col];
                mma_tf32(acc[0][ni], a00.x, a01.x, a00.y, a01.y, bb.x, bb.y);
                mma_tf32(acc[1][ni], a10.x, a11.x, a10.y, a11.y, bb.x, bb.y);
            }
        }
        __syncthreads();
    }

#pragma unroll
    for (int mi = 0; mi < 2; mi++) {
        int rbase = warpM*32 + mi*16 + lq;
#pragma unroll
        for (int ni = 0; ni < 12; ni++) {
            int cc = warpN*96 + ni*8 + 2*lr;
            *(float2*)&sD[(rbase    )*SD_STRIDE + cc] = make_float2(acc[mi][ni][0], acc[mi][ni][1]);
            *(float2*)&sD[(rbase + 8)*SD_STRIDE + cc] = make_float2(acc[mi][ni][2], acc[mi][ni][3]);
        }
    }
    __syncthreads();

    const float* i2hb = g_i2h + (size_t)b*C3*HW;
#pragma unroll
    for (int it = 0; it < 32; it++) {
        int idx = it*256 + tid;
        int c = idx >> 7, px = idx & 127;
        int p = p0 + px;
        if (p < HW) {
            float hr = sD[px*SD_STRIDE + c      ] + __ldg(&h2h_b[c      ]);
            float hu = sD[px*SD_STRIDE + c +  64] + __ldg(&h2h_b[c +  64]);
            float hm = sD[px*SD_STRIDE + c + 128] + __ldg(&h2h_b[c + 128]);
            float ir = i2hb[(size_t)(c      )*HW + p];
            float iu = i2hb[(size_t)(c +  64)*HW + p];
            float im = i2hb[(size_t)(c + 128)*HW + p];
            float hpv = hp[((size_t)b*HID + c)*HW + p];
            float rg = 1.f / (1.f + expf(-(ir + hr)));
            float ug = 1.f / (1.f + expf(-(iu + hu)));
            float nm = tanhf(im + rg * hm);
            out[((size_t)b*HID + c)*HW + p] = ug * hpv + (1.f - ug) * nm;
        }
    }
}

// ---------------- launch ---------------------------------------------------
extern "C" void kernel_launch(void* const* d_in, const int* in_sizes, int n_in,
                              void* d_out, int out_size)
{
    const float* x       = (const float*)d_in[0];
    const float* h_prev  = (const float*)d_in[1];
    const float* i2h_w   = (const float*)d_in[2];
    const float* i2h_b   = (const float*)d_in[3];
    const float* h2h_w   = (const float*)d_in[4];
    const float* h2h_b   = (const float*)d_in[5];
    const float* i2f_w   = (const float*)d_in[6];
    const float* i2f_b   = (const float*)d_in[7];
    const float* h2f_w   = (const float*)d_in[8];
    const float* h2f_b   = (const float*)d_in[9];
    const float* flows_w = (const float*)d_in[10];
    const float* flows_b = (const float*)d_in[11];
    float* out = (float*)d_out;

    cudaFuncSetAttribute(k_main_mma, cudaFuncAttributeMaxDynamicSharedMemorySize,
                         SMEM_MMA_BYTES);
    cudaFuncSetAttribute(k_f_mma, cudaFuncAttributeMaxDynamicSharedMemorySize,
                         KF_SMEM);
    cudaFuncSetAttribute(k_i2h_mma, cudaFuncAttributeMaxDynamicSharedMemorySize,
                         KI_SMEM);

    dim3 gt(HW/32, HID/32, BATCH);
    k_transpose<<<gt, dim3(32, 8)>>>(h_prev);

    dim3 gx(HW/32, 1, BATCH);
    k_xpose<<<gx, dim3(32, 8)>>>(x);

    k_prep_w<<<(25*32*72 + 255)/256, 256>>>(i2f_w, h2f_w);
    k_prep_wB<<<(LNK*192*64 + 255)/256, 256>>>(h2h_w);
    k_prep_wI<<<(192*72 + 255)/256, 256>>>(i2h_w);

    dim3 gfm(HH, BATCH);
    k_f_mma<<<gfm, 256, KF_SMEM>>>(i2f_b, h2f_b);
    k_i2h_mma<<<gfm, 256, KI_SMEM>>>(i2h_b);

    dim3 gfl(30, BATCH);
    k_flows<<<gfl, 240>>>(flows_w, flows_b);

    dim3 gm((HW + 127)/128, BATCH);
    k_main_mma<<<gm, 256, SMEM_MMA_BYTES>>>(h_prev, h2h_b, out);
}

// round 8
// speedup vs baseline: 2.3640x; 1.0171x over previous
#include <cuda_runtime.h>
#include <math.h>
#include <stdint.h>

#define BATCH 8
#define NCIN 8
#define HID 64
#define LNK 9
#define HH 120
#define WW 120
#define HW (HH*WW)      // 14400
#define C3 (3*HID)      // 192

__device__ __forceinline__ uint32_t f2tf32(float v) {
    uint32_t r; asm("cvt.rna.tf32.f32 %0, %1;" : "=r"(r) : "f"(v)); return r;
}
__device__ __forceinline__ void mma_tf32(float* d,
    uint32_t a0, uint32_t a1, uint32_t a2, uint32_t a3,
    uint32_t b0, uint32_t b1)
{
    asm volatile("mma.sync.aligned.m16n8k8.row.col.f32.tf32.tf32.f32 "
        "{%0,%1,%2,%3}, {%4,%5,%6,%7}, {%8,%9}, {%0,%1,%2,%3};"
        : "+f"(d[0]), "+f"(d[1]), "+f"(d[2]), "+f"(d[3])
        : "r"(a0), "r"(a1), "r"(a2), "r"(a3), "r"(b0), "r"(b1));
}
__device__ __forceinline__ float fsigmoid(float x) {
    return 1.f / (1.f + __expf(-x));
}
__device__ __forceinline__ float ftanh(float x) {
    return 1.f - 2.f / (1.f + __expf(2.f*x));
}
// permuted slot within 8-block: q = ((k>>2)&1) + 2*(k&3)
__device__ __forceinline__ int kslot(int k) {
    return (k & ~7) + ((k >> 2) & 1) + 2*(k & 3);
}

// -------- scratch (device globals) ----------------------------------------
__device__ float    g_flows[BATCH*2*LNK*HW];
__device__ float    g_i2h[(size_t)BATCH*C3*HW];
__device__ float4   g_hT4[(size_t)BATCH*HW*16];    // h_prev [b][p][64], fp32, slot-permuted
__device__ uint32_t g_xhT[(size_t)BATCH*HW*72];    // [b][p][72] tf32 permuted: x(8)+h(64)
__device__ uint32_t g_fT[(size_t)BATCH*HW*32];     // f [b][p][32] tf32 permuted
__device__ uint32_t g_wf[25*32*72];                // conv-f weights
__device__ uint32_t g_wB[LNK*192*64];              // h2h weights
__device__ uint32_t g_wI[192*72];                  // i2h weights
__device__ uint32_t g_wFl[25*24*32];               // flows weights (18->24 pad)

// ---------------- transpose h_prev NCHW -> permuted NHWC -------------------
__global__ void k_transpose(const float* __restrict__ hp)
{
    __shared__ float t[32][33];
    int b  = blockIdx.z;
    int c0 = blockIdx.y * 32;
    int p0 = blockIdx.x * 32;
    int tx = threadIdx.x, ty = threadIdx.y;
    float* hT = (float*)g_hT4;
#pragma unroll
    for (int k = 0; k < 4; k++) {
        int c = c0 + ty + k*8;
        t[ty + k*8][tx] = hp[((size_t)b*HID + c)*HW + p0 + tx];
    }
    __syncthreads();
    int c = c0 + tx;
    int slot = kslot(c);
#pragma unroll
    for (int k = 0; k < 4; k++) {
        int p = p0 + ty + k*8;
        float v = t[tx][ty + k*8];
        hT[((size_t)b*HW + p)*HID + slot] = v;
        g_xhT[((size_t)b*HW + p)*72 + 8 + slot] = f2tf32(v);
    }
}

__global__ void k_xpose(const float* __restrict__ x)
{
    int b  = blockIdx.z;
    int p0 = blockIdx.x * 32;
    int tx = threadIdx.x, ty = threadIdx.y;   // (32, 8)
    float v = x[((size_t)b*NCIN + ty)*HW + p0 + tx];
    g_xhT[((size_t)b*HW + p0 + tx)*72 + kslot(ty & 7) ] = f2tf32(v);
}

__global__ void k_prep_w(const float* __restrict__ i2f_w,
                         const float* __restrict__ h2f_w)
{
    int idx = blockIdx.x*256 + threadIdx.x;
    if (idx >= 25*32*72) return;
    int t  = idx / (32*72);
    int r  = idx % (32*72);
    int oc = r / 72, k = r % 72;
    float v = (k < 8) ? i2f_w[((size_t)oc*NCIN + k)*25 + t]
                      : h2f_w[((size_t)oc*HID + (k-8))*25 + t];
    g_wf[t*(32*72) + oc*72 + kslot(k)] = f2tf32(v);
}

__global__ void k_prep_wB(const float* __restrict__ h2h_w)
{
    int idx = blockIdx.x*256 + threadIdx.x;
    if (idx >= LNK*192*64) return;
    int l = idx / (192*64);
    int r = idx % (192*64);
    int o = r / 64, p = r % 64;
    int k = (p & ~7) + ((p & 1) << 2) + ((p & 7) >> 1);
    g_wB[idx] = f2tf32(h2h_w[(size_t)o*576 + l*64 + k]);
}

__global__ void k_prep_wI(const float* __restrict__ i2h_w)
{
    int idx = blockIdx.x*256 + threadIdx.x;
    if (idx >= 192*72) return;
    int o = idx / 72, p = idx % 72;
    int t = p >> 3, q = p & 7;
    int c = ((q & 1) << 2) + (q >> 1);
    g_wI[idx] = f2tf32(i2h_w[(size_t)o*72 + c*9 + t]);
}

// flows weights -> g_wFl[t][24][32] tf32 permuted (oc 18..23 zero)
__global__ void k_prep_wFl(const float* __restrict__ flows_w)
{
    int idx = blockIdx.x*256 + threadIdx.x;
    if (idx >= 25*24*32) return;
    int t = idx / (24*32);
    int r = idx % (24*32);
    int o = r / 32, p = r % 32;
    int c = (p & ~7) + ((p & 1) << 2) + ((p & 7) >> 1);
    uint32_t v = 0u;
    if (o < 18) v = f2tf32(flows_w[(size_t)o*(32*25) + c*25 + t]);
    g_wFl[t*(24*32) + o*32 + p] = v;
}

// ==========================================================================
// k_f_mma: f = relu(conv5x5(xh; wf)) -> g_fT (channels-last tf32 permuted)
// ==========================================================================
#define KF_AS 76
#define KF_AROWS 132
#define KF_OFF_B (KF_AROWS*KF_AS*4)               // 40128
#define KF_SMEM  (KF_OFF_B + 160*KF_AS*4)         // 88768

__global__ __launch_bounds__(256, 2) void k_f_mma(
    const float* __restrict__ i2f_b, const float* __restrict__ h2f_b)
{
    extern __shared__ char sm[];
    uint32_t* sA = (uint32_t*)sm;
    uint32_t* sB = (uint32_t*)(sm + KF_OFF_B);

    int b   = blockIdx.y;
    int y0  = blockIdx.x;
    int tid = threadIdx.x;
    int wid = tid >> 5, lane = tid & 31;
    int warpM = wid & 3, warpN = wid >> 2;
    int lq = lane >> 2, lr = lane & 3;

    float acc[2][2][4];
#pragma unroll
    for (int mi = 0; mi < 2; mi++)
#pragma unroll
        for (int ni = 0; ni < 2; ni++)
#pragma unroll
            for (int j = 0; j < 4; j++) acc[mi][ni][j] = 0.f;

    for (int i = tid; i < 8*KF_AS; i += 256)
        sA[124*KF_AS + i] = 0;

    const uint4* xh4 = (const uint4*)(g_xhT + (size_t)b*HW*72);

    for (int dy = 0; dy < 5; dy++) {
        __syncthreads();
        int iy = y0 + dy - 2;
        for (int idx = tid; idx < 124*18; idx += 256) {
            int col = idx / 18, kq = idx % 18;
            int gx = col - 2;
            uint4 v = make_uint4(0u, 0u, 0u, 0u);
            if (iy >= 0 && iy < HH && gx >= 0 && gx < WW)
                v = xh4[((size_t)iy*WW + gx)*18 + kq];
            *(uint4*)&sA[col*KF_AS + kq*4] = v;
        }
        const uint4* wsrc = (const uint4*)&g_wf[dy*5*(32*72)];
        for (int idx = tid; idx < 5*32*18; idx += 256) {
            int row = idx / 18, kq = idx % 18;
            *(uint4*)&sB[row*KF_AS + kq*4] = wsrc[row*18 + kq];
        }
        __syncthreads();

#pragma unroll
        for (int dx = 0; dx < 5; dx++) {
            const uint32_t* Ab = sA + (warpM*32 + dx + lq)*KF_AS;
            const uint32_t* Bb = sB + (dx*32 + warpN*16 + lq)*KF_AS;
#pragma unroll
            for (int kb = 0; kb < 9; kb++) {
                int col = kb*8 + 2*lr;
                uint2 a00 = *(const uint2*)&Ab[col];
                uint2 a01 = *(const uint2*)&Ab[ 8*KF_AS + col];
                uint2 a10 = *(const uint2*)&Ab[16*KF_AS + col];
                uint2 a11 = *(const uint2*)&Ab[24*KF_AS + col];
                uint2 b0  = *(const uint2*)&Bb[col];
                uint2 b1  = *(const uint2*)&Bb[ 8*KF_AS + col];
                mma_tf32(acc[0][0], a00.x, a01.x, a00.y, a01.y, b0.x, b0.y);
                mma_tf32(acc[0][1], a00.x, a01.x, a00.y, a01.y, b1.x, b1.y);
                mma_tf32(acc[1][0], a10.x, a11.x, a10.y, a11.y, b0.x, b0.y);
                mma_tf32(acc[1][1], a10.x, a11.x, a10.y, a11.y, b1.x, b1.y);
            }
        }
    }

    // epilogue: bias+relu -> stage to sA as [px][32] tf32 -> copy to g_fT
    __syncthreads();
#pragma unroll
    for (int ni = 0; ni < 2; ni++) {
        int ocA = warpN*16 + ni*8 + 2*lr, ocB = ocA + 1;
        int sA_ = kslot(ocA), sB_ = kslot(ocB);
        float bA = __ldg(&i2f_b[ocA]) + __ldg(&h2f_b[ocA]);
        float bB = __ldg(&i2f_b[ocB]) + __ldg(&h2f_b[ocB]);
#pragma unroll
        for (int mi = 0; mi < 2; mi++) {
            int x0 = warpM*32 + mi*16 + lq;
            int x1 = x0 + 8;
            sA[x0*32 + sA_] = f2tf32(fmaxf(acc[mi][ni][0] + bA, 0.f));
            sA[x0*32 + sB_] = f2tf32(fmaxf(acc[mi][ni][1] + bB, 0.f));
            sA[x1*32 + sA_] = f2tf32(fmaxf(acc[mi][ni][2] + bA, 0.f));
            sA[x1*32 + sB_] = f2tf32(fmaxf(acc[mi][ni][3] + bB, 0.f));
        }
    }
    __syncthreads();
    uint4* fT4 = (uint4*)(g_fT + ((size_t)b*HW + (size_t)y0*WW)*32);
    for (int idx = tid; idx < 120*8; idx += 256)
        fT4[idx] = ((const uint4*)sA)[idx];
}

// ==========================================================================
// k_flows_mma: flows = conv5x5(f; wFl), 32 ch -> 18(24) oc, mma tf32
// CTA = 1 output row (128 px over 8 warps) x 24 oc, 256 thr.
// ==========================================================================
#define KFL_AS 36
__global__ __launch_bounds__(256, 2) void k_flows_mma(const float* __restrict__ flows_b)
{
    __shared__ uint32_t sA[KF_AROWS*KFL_AS];     // 132 x 36
    __shared__ uint32_t sB[120*KFL_AS];          // 5dx x 24oc

    int b   = blockIdx.y;
    int y0  = blockIdx.x;
    int tid = threadIdx.x;
    int wid = tid >> 5, lane = tid & 31;
    int lq = lane >> 2, lr = lane & 3;

    float acc[3][4];
#pragma unroll
    for (int ni = 0; ni < 3; ni++)
#pragma unroll
        for (int j = 0; j < 4; j++) acc[ni][j] = 0.f;

    for (int i = tid; i < 8*KFL_AS; i += 256)
        sA[124*KFL_AS + i] = 0;

    const uint4* fT4 = (const uint4*)(g_fT + (size_t)b*HW*32);

    for (int dy = 0; dy < 5; dy++) {
        __syncthreads();
        int iy = y0 + dy - 2;
        for (int idx = tid; idx < 124*8; idx += 256) {
            int col = idx >> 3, kq = idx & 7;
            int gx = col - 2;
            uint4 v = make_uint4(0u, 0u, 0u, 0u);
            if (iy >= 0 && iy < HH && gx >= 0 && gx < WW)
                v = fT4[((size_t)iy*WW + gx)*8 + kq];
            *(uint4*)&sA[col*KFL_AS + kq*4] = v;
        }
        const uint4* wsrc = (const uint4*)&g_wFl[dy*5*(24*32)];
        for (int idx = tid; idx < 5*24*8; idx += 256) {
            int row = idx >> 3, kq = idx & 7;
            *(uint4*)&sB[row*KFL_AS + kq*4] = wsrc[idx];
        }
        __syncthreads();

#pragma unroll
        for (int dx = 0; dx < 5; dx++) {
            const uint32_t* Ab = sA + (wid*16 + dx + lq)*KFL_AS;
            const uint32_t* Bb = sB + (dx*24 + lq)*KFL_AS;
#pragma unroll
            for (int kb = 0; kb < 4; kb++) {
                int col = kb*8 + 2*lr;
                uint2 a0 = *(const uint2*)&Ab[col];
                uint2 a1 = *(const uint2*)&Ab[8*KFL_AS + col];
#pragma unroll
                for (int ni = 0; ni < 3; ni++) {
                    uint2 bb = *(const uint2*)&Bb[ni*8*KFL_AS + col];
                    mma_tf32(acc[ni], a0.x, a1.x, a0.y, a1.y, bb.x, bb.y);
                }
            }
        }
    }

    // epilogue -> g_flows NCHW (oc < 18 only)
    int x0 = wid*16 + lq, x1 = x0 + 8;
#pragma unroll
    for (int ni = 0; ni < 3; ni++) {
        int ocA = ni*8 + 2*lr, ocB = ocA + 1;
        if (ocA < 18) {
            float bias = __ldg(&flows_b[ocA]);
            float* o = &g_flows[((size_t)b*(2*LNK) + ocA)*HW + (size_t)y0*WW];
            if (x0 < WW) o[x0] = acc[ni][0] + bias;
            if (x1 < WW) o[x1] = acc[ni][2] + bias;
        }
        if (ocB < 18) {
            float bias = __ldg(&flows_b[ocB]);
            float* o = &g_flows[((size_t)b*(2*LNK) + ocB)*HW + (size_t)y0*WW];
            if (x0 < WW) o[x0] = acc[ni][1] + bias;
            if (x1 < WW) o[x1] = acc[ni][3] + bias;
        }
    }
}

// ==========================================================================
// k_i2h_mma: i2h = conv3x3(x; i2h_w) via mma.sync tf32
// ==========================================================================
#define KI_AS 76
#define KI_OFF_B (128*KI_AS*4)                    // 38912
#define KI_SMEM  (KI_OFF_B + 192*KI_AS*4)         // 97280

__global__ __launch_bounds__(256, 1) void k_i2h_mma(const float* __restrict__ i2h_b)
{
    extern __shared__ char sm[];
    uint32_t* sA = (uint32_t*)sm;
    uint32_t* sB = (uint32_t*)(sm + KI_OFF_B);

    int b   = blockIdx.y;
    int y0  = blockIdx.x;
    int tid = threadIdx.x;
    int wid = tid >> 5, lane = tid & 31;
    int warpM = wid & 3, warpN = wid >> 2;
    int lq = lane >> 2, lr = lane & 3;

    const uint4* xh4 = (const uint4*)(g_xhT + (size_t)b*HW*72);

    for (int idx = tid; idx < 128*18; idx += 256) {
        int px = idx / 18, r = idx % 18;
        int t = r >> 1, half = r & 1;
        int dy = t / 3, dx = t % 3;
        int iy = y0 + dy - 1, gx = px + dx - 1;
        uint4 v = make_uint4(0u, 0u, 0u, 0u);
        if (iy >= 0 && iy < HH && gx >= 0 && gx < WW)
            v = xh4[((size_t)iy*WW + gx)*18 + half];
        *(uint4*)&sA[px*KI_AS + t*8 + half*4] = v;
    }
    {
        const uint4* wI4 = (const uint4*)g_wI;
        for (int idx = tid; idx < 192*18; idx += 256) {
            int o = idx / 18, kq = idx % 18;
            *(uint4*)&sB[o*KI_AS + kq*4] = wI4[idx];
        }
    }
    __syncthreads();

    float acc[2][12][4];
#pragma unroll
    for (int mi = 0; mi < 2; mi++)
#pragma unroll
        for (int ni = 0; ni < 12; ni++)
#pragma unroll
            for (int j = 0; j < 4; j++) acc[mi][ni][j] = 0.f;

    const uint32_t* Ab = sA + (warpM*32 + lq)*KI_AS;
    const uint32_t* Bb = sB + (warpN*96 + lq)*KI_AS;
#pragma unroll
    for (int kb = 0; kb < 9; kb++) {
        int col = kb*8 + 2*lr;
        uint2 a00 = *(const uint2*)&Ab[col];
        uint2 a01 = *(const uint2*)&Ab[ 8*KI_AS + col];
        uint2 a10 = *(const uint2*)&Ab[16*KI_AS + col];
        uint2 a11 = *(const uint2*)&Ab[24*KI_AS + col];
#pragma unroll
        for (int ni = 0; ni < 12; ni++) {
            uint2 bb = *(const uint2*)&Bb[ni*8*KI_AS + col];
            mma_tf32(acc[0][ni], a00.x, a01.x, a00.y, a01.y, bb.x, bb.y);
            mma_tf32(acc[1][ni], a10.x, a11.x, a10.y, a11.y, bb.x, bb.y);
        }
    }

#pragma unroll
    for (int ni = 0; ni < 12; ni++) {
        int ocA = warpN*96 + ni*8 + 2*lr, ocB = ocA + 1;
        float bA = __ldg(&i2h_b[ocA]);
        float bB = __ldg(&i2h_b[ocB]);
        float* oA = &g_i2h[((size_t)b*C3 + ocA)*HW + (size_t)y0*WW];
        float* oB = &g_i2h[((size_t)b*C3 + ocB)*HW + (size_t)y0*WW];
#pragma unroll
        for (int mi = 0; mi < 2; mi++) {
            int x0 = warpM*32 + mi*16 + lq;
            int x1 = x0 + 8;
            if (x0 < WW) {
                oA[x0] = acc[mi][ni][0] + bA;
                oB[x0] = acc[mi][ni][1] + bB;
            }
            if (x1 < WW) {
                oA[x1] = acc[mi][ni][2] + bA;
                oB[x1] = acc[mi][ni][3] + bB;
            }
        }
    }
}

// ==========================================================================
// k_main: fused warp(x9) + 1x1 conv via mma.sync tf32 + GRU gates
// ==========================================================================
#define SA_STRIDE 72
#define SB_STRIDE 72
#define OFF_GEO 0
#define OFF_A   4096
#define OFF_B   (OFF_A + 128*SA_STRIDE*4)          // 40960
#define PHASE1_BYTES (OFF_B + 192*SB_STRIDE*4)     // 96256
#define SD_STRIDE 194
#define SD_BYTES (128*SD_STRIDE*4)                 // 99328
#define SMEM_MMA_BYTES (SD_BYTES > PHASE1_BYTES ? SD_BYTES : PHASE1_BYTES)

__global__ __launch_bounds__(256, 1) void k_main_mma(
    const float* __restrict__ hp,
    const float* __restrict__ h2h_b,
    float* __restrict__ out)
{
    extern __shared__ char sm[];
    float*    sgeo = (float*)(sm + OFF_GEO);
    uint32_t* sA   = (uint32_t*)(sm + OFF_A);
    uint32_t* sB   = (uint32_t*)(sm + OFF_B);
    float*    sD   = (float*)sm;

    int b   = blockIdx.y;
    int p0  = blockIdx.x * 128;
    int tid = threadIdx.x;
    int wid = tid >> 5, lane = tid & 31;
    int warpM = wid & 3, warpN = wid >> 2;
    int lq = lane >> 2, lr = lane & 3;

    float acc[2][12][4];
#pragma unroll
    for (int mi = 0; mi < 2; mi++)
#pragma unroll
        for (int ni = 0; ni < 12; ni++)
#pragma unroll
            for (int j = 0; j < 4; j++) acc[mi][ni][j] = 0.f;

    const float4* hT4 = g_hT4 + (size_t)b*HW*16;

    for (int l = 0; l < LNK; l++) {
        if (tid < 128) {
            int p = p0 + tid; if (p > HW-1) p = HW-1;
            int yc = p / WW, xc = p - yc*WW;
            float sx = (float)xc + g_flows[((size_t)b*(2*LNK) + 2*l    )*HW + p];
            float sy = (float)yc + g_flows[((size_t)b*(2*LNK) + 2*l + 1)*HW + p];
            float fx = floorf(sx), fy = floorf(sy);
            float wx1 = sx - fx, wy1 = sy - fy;
            float wx0 = 1.f - wx1, wy0 = 1.f - wy1;
            int ix0 = (int)fx, iy0 = (int)fy;
            bool vx0 = (ix0 >= 0) && (ix0 < WW);
            bool vx1 = (ix0 >= -1) && (ix0 < WW - 1);
            bool vy0 = (iy0 >= 0) && (iy0 < HH);
            bool vy1 = (iy0 >= -1) && (iy0 < HH - 1);
            int r0 = iy0*WW, r1 = r0 + WW;
            float* g = &sgeo[tid*8];
            g[0] = wy0*wx0; g[1] = wy0*wx1; g[2] = wy1*wx0; g[3] = wy1*wx1;
            ((int*)g)[4] = (vy0 && vx0) ? (r0 + ix0)     : -1;
            ((int*)g)[5] = (vy0 && vx1) ? (r0 + ix0 + 1) : -1;
            ((int*)g)[6] = (vy1 && vx0) ? (r1 + ix0)     : -1;
            ((int*)g)[7] = (vy1 && vx1) ? (r1 + ix0 + 1) : -1;
        }
        __syncthreads();

        {
            const uint4* wB4 = (const uint4*)&g_wB[(size_t)l*192*64];
#pragma unroll
            for (int i = 0; i < 12; i++) {
                int q = i*256 + tid;
                int o = q >> 4, kq = q & 15;
                *(uint4*)&sB[o*SB_STRIDE + kq*4] = wB4[o*16 + kq];
            }
        }

#pragma unroll
        for (int i = 0; i < 8; i++) {
            int item = i*256 + tid;
            int px = item >> 4, cg = item & 15;
            const float* g = &sgeo[px*8];
            float w00 = g[0], w01 = g[1], w10 = g[2], w11 = g[3];
            int i00 = ((const int*)g)[4], i01 = ((const int*)g)[5];
            int i10 = ((const int*)g)[6], i11 = ((const int*)g)[7];
            float ax=0.f, ay=0.f, az=0.f, aw=0.f;
            if (i00 >= 0) { float4 v = hT4[(size_t)i00*16 + cg];
                ax += w00*v.x; ay += w00*v.y; az += w00*v.z; aw += w00*v.w; }
            if (i01 >= 0) { float4 v = hT4[(size_t)i01*16 + cg];
                ax += w01*v.x; ay += w01*v.y; az += w01*v.z; aw += w01*v.w; }
            if (i10 >= 0) { float4 v = hT4[(size_t)i10*16 + cg];
                ax += w10*v.x; ay += w10*v.y; az += w10*v.z; aw += w10*v.w; }
            if (i11 >= 0) { float4 v = hT4[(size_t)i11*16 + cg];
                ax += w11*v.x; ay += w11*v.y; az += w11*v.z; aw += w11*v.w; }
            uint4 t;
            t.x = f2tf32(ax); t.y = f2tf32(ay); t.z = f2tf32(az); t.w = f2tf32(aw);
            *(uint4*)&sA[px*SA_STRIDE + cg*4] = t;
        }
        __syncthreads();

        const uint32_t* Ab = sA + (warpM*32 + lq)*SA_STRIDE;
        const uint32_t* Bb = sB + (warpN*96 + lq)*SB_STRIDE;
#pragma unroll
        for (int kb = 0; kb < 8; kb++) {
            int col = kb*8 + 2*lr;
            uint2 a00 = *(const uint2*)&Ab[col];
            uint2 a01 = *(const uint2*)&Ab[8*SA_STRIDE + col];
            uint2 a10 = *(const uint2*)&Ab[16*SA_STRIDE + col];
            uint2 a11 = *(const uint2*)&Ab[24*SA_STRIDE + col];
#pragma unroll
            for (int ni = 0; ni < 12; ni++) {
                uint2 bb = *(const uint2*)&Bb[ni*8*SB_STRIDE + col];
                mma_tf32(acc[0][ni], a00.x, a01.x, a00.y, a01.y, bb.x, bb.y);
                mma_tf32(acc[1][ni], a10.x, a11.x, a10.y, a11.y, bb.x, bb.y);
            }
        }
        __syncthreads();
    }

#pragma unroll
    for (int mi = 0; mi < 2; mi++) {
        int rbase = warpM*32 + mi*16 + lq;
#pragma unroll
        for (int ni = 0; ni < 12; ni++) {
            int cc = warpN*96 + ni*8 + 2*lr;
            *(float2*)&sD[(rbase    )*SD_STRIDE + cc] = make_float2(acc[mi][ni][0], acc[mi][ni][1]);
            *(float2*)&sD[(rbase + 8)*SD_STRIDE + cc] = make_float2(acc[mi][ni][2], acc[mi][ni][3]);
        }
    }
    __syncthreads();

    const float* i2hb = g_i2h + (size_t)b*C3*HW;
#pragma unroll
    for (int it = 0; it < 32; it++) {
        int idx = it*256 + tid;
        int c = idx >> 7, px = idx & 127;
        int p = p0 + px;
        if (p < HW) {
            float hr = sD[px*SD_STRIDE + c      ] + __ldg(&h2h_b[c      ]);
            float hu = sD[px*SD_STRIDE + c +  64] + __ldg(&h2h_b[c +  64]);
            float hm = sD[px*SD_STRIDE + c + 128] + __ldg(&h2h_b[c + 128]);
            float ir = i2hb[(size_t)(c      )*HW + p];
            float iu = i2hb[(size_t)(c +  64)*HW + p];
            float im = i2hb[(size_t)(c + 128)*HW + p];
            float hpv = hp[((size_t)b*HID + c)*HW + p];
            float rg = fsigmoid(ir + hr);
            float ug = fsigmoid(iu + hu);
            float nm = ftanh(im + rg * hm);
            out[((size_t)b*HID + c)*HW + p] = ug * hpv + (1.f - ug) * nm;
        }
    }
}

// ---------------- launch ---------------------------------------------------
extern "C" void kernel_launch(void* const* d_in, const int* in_sizes, int n_in,
                              void* d_out, int out_size)
{
    const float* x       = (const float*)d_in[0];
    const float* h_prev  = (const float*)d_in[1];
    const float* i2h_w   = (const float*)d_in[2];
    const float* i2h_b   = (const float*)d_in[3];
    const float* h2h_w   = (const float*)d_in[4];
    const float* h2h_b   = (const float*)d_in[5];
    const float* i2f_w   = (const float*)d_in[6];
    const float* i2f_b   = (const float*)d_in[7];
    const float* h2f_w   = (const float*)d_in[8];
    const float* h2f_b   = (const float*)d_in[9];
    const float* flows_w = (const float*)d_in[10];
    const float* flows_b = (const float*)d_in[11];
    float* out = (float*)d_out;

    cudaFuncSetAttribute(k_main_mma, cudaFuncAttributeMaxDynamicSharedMemorySize,
                         SMEM_MMA_BYTES);
    cudaFuncSetAttribute(k_f_mma, cudaFuncAttributeMaxDynamicSharedMemorySize,
                         KF_SMEM);
    cudaFuncSetAttribute(k_i2h_mma, cudaFuncAttributeMaxDynamicSharedMemorySize,
                         KI_SMEM);

    dim3 gt(HW/32, HID/32, BATCH);
    k_transpose<<<gt, dim3(32, 8)>>>(h_prev);

    dim3 gx(HW/32, 1, BATCH);
    k_xpose<<<gx, dim3(32, 8)>>>(x);

    k_prep_w<<<(25*32*72 + 255)/256, 256>>>(i2f_w, h2f_w);
    k_prep_wB<<<(LNK*192*64 + 255)/256, 256>>>(h2h_w);
    k_prep_wI<<<(192*72 + 255)/256, 256>>>(i2h_w);
    k_prep_wFl<<<(25*24*32 + 255)/256, 256>>>(flows_w);

    dim3 gfm(HH, BATCH);
    k_f_mma<<<gfm, 256, KF_SMEM>>>(i2f_b, h2f_b);
    k_i2h_mma<<<gfm, 256, KI_SMEM>>>(i2h_b);
    k_flows_mma<<<gfm, 256>>>(flows_b);

    dim3 gm((HW + 127)/128, BATCH);
    k_main_mma<<<gm, 256, SMEM_MMA_BYTES>>>(h_prev, h2h_b, out);
}